// round 3
// baseline (speedup 1.0000x reference)
#include <cuda_runtime.h>
#include <math.h>

#define NTOK  197
#define BATCH 256
#define CDIM  768
#define NH    12
#define HD    64
#define LKEEP 98
#define NP    (NTOK - 1)     // 196
#define NNEW  (LKEEP + 2)    // 100
#define M1    (NTOK * BATCH) // 50432
#define M2    (NNEW * BATCH) // 25600

typedef unsigned long long u64;

// ---------------- scratch (device globals; no cudaMalloc allowed) ----------
__device__ float g_ln1 [(size_t)M1 * CDIM];
__device__ float g_qkv [(size_t)M1 * 3 * CDIM];
__device__ float g_att [(size_t)M1 * CDIM];
__device__ float g_xres[(size_t)M1 * CDIM];
__device__ float g_cls [(size_t)BATCH * NP];
__device__ int   g_idx [BATCH * LKEEP];
__device__ int   g_comp[BATCH * LKEEP];
__device__ float g_xnew[(size_t)M2 * CDIM];
__device__ float g_ln2 [(size_t)M2 * CDIM];
__device__ float g_fc  [(size_t)M2 * 4 * CDIM];

// ---------------- packed f32x2 helpers (Blackwell FFMA2 path) --------------
__device__ __forceinline__ void fma2(u64& acc, u64 a, u64 b) {
    asm("fma.rn.f32x2 %0, %1, %2, %0;" : "+l"(acc) : "l"(a), "l"(b));
}
__device__ __forceinline__ u64 dup2(float x) {
    u64 r; unsigned xi = __float_as_uint(x);
    asm("mov.b64 %0, {%1, %1};" : "=l"(r) : "r"(xi));
    return r;
}

// ---------------- layernorm: one block per row of 768 ----------------------
__global__ void ln_kernel(const float* __restrict__ x,
                          const float* __restrict__ gam,
                          const float* __restrict__ bet,
                          float* __restrict__ y)
{
    const int row = blockIdx.x;
    const int t   = threadIdx.x;               // 256 threads, 3 elems each
    const float* xr = x + (size_t)row * CDIM;
    float*       yr = y + (size_t)row * CDIM;

    float v0 = xr[t], v1 = xr[t + 256], v2 = xr[t + 512];
    float s  = v0 + v1 + v2;
    float ss = v0 * v0 + v1 * v1 + v2 * v2;

    __shared__ float red[16];
    #pragma unroll
    for (int o = 16; o; o >>= 1) {
        s  += __shfl_xor_sync(0xffffffffu, s,  o);
        ss += __shfl_xor_sync(0xffffffffu, ss, o);
    }
    const int warp = t >> 5, lane = t & 31;
    if (lane == 0) { red[warp] = s; red[warp + 8] = ss; }
    __syncthreads();
    float S = 0.f, SS = 0.f;
    #pragma unroll
    for (int i = 0; i < 8; i++) { S += red[i]; SS += red[i + 8]; }

    const float mu  = S * (1.f / CDIM);
    const float var = SS * (1.f / CDIM) - mu * mu;
    const float inv = rsqrtf(var + 1e-5f);

    yr[t]       = (v0 - mu) * inv * gam[t]       + bet[t];
    yr[t + 256] = (v1 - mu) * inv * gam[t + 256] + bet[t + 256];
    yr[t + 512] = (v2 - mu) * inv * gam[t + 512] + bet[t + 512];
}

// ---------------- SGEMM (FFMA2): C[M,N] = A[M,K] @ W[N,K]^T + bias ---------
// 128x128 block tile, BK=8, 256 threads, 8x8 per thread, packed f32x2 math,
// double-buffered smem (one barrier per K-tile).
__global__ void __launch_bounds__(256, 2)
sgemm_kernel(const float* __restrict__ A, const float* __restrict__ W,
             const float* __restrict__ bias, const float* __restrict__ res,
             float* __restrict__ C, int M, int Nn, int K, int act)
{
    __shared__ __align__(16) float As[2][8][132];
    __shared__ __align__(16) float Bs[2][8][132];

    const int tid  = threadIdx.x;
    const int m0   = blockIdx.y * 128;
    const int n0   = blockIdx.x * 128;
    const int tx   = tid & 15;
    const int ty   = tid >> 4;
    const int lrow = tid >> 1;           // 0..127
    const int lk   = (tid & 1) * 4;      // 0 or 4

    const float* Ap = A + (size_t)(m0 + lrow) * K + lk;
    const float* Wp = W + (size_t)(n0 + lrow) * K + lk;

    u64 acc2[8][4];
    #pragma unroll
    for (int i = 0; i < 8; i++)
        #pragma unroll
        for (int j = 0; j < 4; j++) acc2[i][j] = 0ULL;

    // preload tile 0
    float4 av = *(const float4*)Ap;
    float4 bv = *(const float4*)Wp;
    As[0][lk + 0][lrow] = av.x; As[0][lk + 1][lrow] = av.y;
    As[0][lk + 2][lrow] = av.z; As[0][lk + 3][lrow] = av.w;
    Bs[0][lk + 0][lrow] = bv.x; Bs[0][lk + 1][lrow] = bv.y;
    Bs[0][lk + 2][lrow] = bv.z; Bs[0][lk + 3][lrow] = bv.w;
    __syncthreads();

    const int T = K / 8;
    int buf = 0;
    for (int t = 0; t < T; t++) {
        if (t + 1 < T) {                 // prefetch next tile from gmem
            av = *(const float4*)(Ap + (t + 1) * 8);
            bv = *(const float4*)(Wp + (t + 1) * 8);
        }
        #pragma unroll
        for (int k = 0; k < 8; k++) {
            float4 t0 = *(const float4*)&As[buf][k][ty * 8];
            float4 t1 = *(const float4*)&As[buf][k][ty * 8 + 4];
            float ar[8] = { t0.x, t0.y, t0.z, t0.w, t1.x, t1.y, t1.z, t1.w };
            ulonglong2 b01 = *(const ulonglong2*)&Bs[buf][k][tx * 8];
            ulonglong2 b23 = *(const ulonglong2*)&Bs[buf][k][tx * 8 + 4];
            u64 br2[4] = { b01.x, b01.y, b23.x, b23.y };
            #pragma unroll
            for (int i = 0; i < 8; i++) {
                const u64 a2 = dup2(ar[i]);
                fma2(acc2[i][0], a2, br2[0]);
                fma2(acc2[i][1], a2, br2[1]);
                fma2(acc2[i][2], a2, br2[2]);
                fma2(acc2[i][3], a2, br2[3]);
            }
        }
        if (t + 1 < T) {
            const int nb = buf ^ 1;
            As[nb][lk + 0][lrow] = av.x; As[nb][lk + 1][lrow] = av.y;
            As[nb][lk + 2][lrow] = av.z; As[nb][lk + 3][lrow] = av.w;
            Bs[nb][lk + 0][lrow] = bv.x; Bs[nb][lk + 1][lrow] = bv.y;
            Bs[nb][lk + 2][lrow] = bv.z; Bs[nb][lk + 3][lrow] = bv.w;
            __syncthreads();
            buf = nb;
        }
    }

    // epilogue: unpack pairs, bias (+quickgelu) (+residual), vectorized stores
    #pragma unroll
    for (int i = 0; i < 8; i++) {
        const int m = m0 + ty * 8 + i;
        const size_t rowb = (size_t)m * Nn + n0 + tx * 8;
        #pragma unroll
        for (int jj = 0; jj < 2; jj++) {
            float v[4];
            #pragma unroll
            for (int j2 = 0; j2 < 2; j2++) {
                const u64 p = acc2[i][jj * 2 + j2];
                v[j2 * 2 + 0] = __uint_as_float((unsigned)(p & 0xffffffffu));
                v[j2 * 2 + 1] = __uint_as_float((unsigned)(p >> 32));
            }
            #pragma unroll
            for (int j = 0; j < 4; j++) {
                const int n = n0 + tx * 8 + jj * 4 + j;
                float tv = v[j] + bias[n];
                if (act) tv = tv / (1.f + __expf(-1.702f * tv));
                v[j] = tv;
            }
            if (res) {
                float4 r = *(const float4*)(res + rowb + jj * 4);
                v[0] += r.x; v[1] += r.y; v[2] += r.z; v[3] += r.w;
            }
            float4 o; o.x = v[0]; o.y = v[1]; o.z = v[2]; o.w = v[3];
            *(float4*)(C + rowb + jj * 4) = o;
        }
    }
}

// ---------------- attention: one CTA per (b,h), K/V resident in smem -------
#define KVPAD 65
#define ATT_SMEM ((2 * NTOK * KVPAD + 8 * NTOK + 8 * HD) * (int)sizeof(float))

__global__ void __launch_bounds__(256)
attn_kernel(const float* __restrict__ qkv, float* __restrict__ out)
{
    extern __shared__ float sm[];
    float* Ks = sm;                       // [NTOK][65]
    float* Vs = Ks + NTOK * KVPAD;        // [NTOK][65]
    float* Ps = Vs + NTOK * KVPAD;        // [8][NTOK]
    float* Qs = Ps + 8 * NTOK;            // [8][64]

    const int b = blockIdx.x, h = blockIdx.y;
    const int tid = threadIdx.x, lane = tid & 31, warp = tid >> 5;

    // load K and V tiles (coalesced per 64-float row chunk)
    for (int idx = tid; idx < NTOK * HD; idx += 256) {
        const int j = idx >> 6, d = idx & 63;
        const size_t g = ((size_t)j * BATCH + b) * (3 * CDIM) + h * HD + d;
        Ks[j * KVPAD + d] = qkv[g + CDIM];
        Vs[j * KVPAD + d] = qkv[g + 2 * CDIM];
    }
    __syncthreads();

    for (int i = warp; i < NTOK; i += 8) {
        // stage q_i
        const size_t qg = ((size_t)i * BATCH + b) * (3 * CDIM) + h * HD;
        Qs[warp * HD + lane]      = qkv[qg + lane];
        Qs[warp * HD + lane + 32] = qkv[qg + lane + 32];
        __syncwarp();

        // scores: lane handles j = lane + 32t
        float s[7];
        #pragma unroll
        for (int t = 0; t < 7; t++) s[t] = 0.f;
        #pragma unroll 8
        for (int d = 0; d < HD; d++) {
            const float qd = Qs[warp * HD + d];
            #pragma unroll
            for (int t = 0; t < 7; t++) {
                const int j = lane + t * 32;
                if (j < NTOK) s[t] += qd * Ks[j * KVPAD + d];
            }
        }
        float mx = -1e30f;
        #pragma unroll
        for (int t = 0; t < 7; t++) {
            const int j = lane + t * 32;
            s[t] = (j < NTOK) ? s[t] * 0.125f : -1e30f;
            mx = fmaxf(mx, s[t]);
        }
        #pragma unroll
        for (int o = 16; o; o >>= 1) mx = fmaxf(mx, __shfl_xor_sync(0xffffffffu, mx, o));
        float sum = 0.f;
        #pragma unroll
        for (int t = 0; t < 7; t++) {
            const int j = lane + t * 32;
            const float e = (j < NTOK) ? __expf(s[t] - mx) : 0.f;
            s[t] = e; sum += e;
        }
        #pragma unroll
        for (int o = 16; o; o >>= 1) sum += __shfl_xor_sync(0xffffffffu, sum, o);
        const float inv = 1.f / sum;
        #pragma unroll
        for (int t = 0; t < 7; t++) {
            const int j = lane + t * 32;
            if (j < NTOK) Ps[warp * NTOK + j] = s[t] * inv;
        }
        __syncwarp();

        // o = P @ V : lane owns dims (lane, lane+32)
        float a0 = 0.f, a1 = 0.f;
        #pragma unroll 4
        for (int j = 0; j < NTOK; j++) {
            const float p = Ps[warp * NTOK + j];
            a0 += p * Vs[j * KVPAD + lane];
            a1 += p * Vs[j * KVPAD + lane + 32];
        }
        const size_t og = ((size_t)i * BATCH + b) * CDIM + h * HD;
        out[og + lane]      = a0;
        out[og + lane + 32] = a1;
        __syncwarp();
    }
}

// ---------------- CLS-row attention in fp64 (ranking-critical) --------------
__global__ void __launch_bounds__(256)
cls_attn_kernel(const float* __restrict__ qkv, float* __restrict__ cls)
{
    const int b = blockIdx.x, t = threadIdx.x;
    __shared__ float  q0s[HD];
    __shared__ double sc[NTOK];
    __shared__ double red[2];

    double acc = 0.0;
    for (int h = 0; h < NH; h++) {
        __syncthreads();
        if (t < HD) q0s[t] = qkv[(size_t)b * (3 * CDIM) + h * HD + t];
        __syncthreads();
        if (t < NTOK) {
            const float* kp = qkv + ((size_t)t * BATCH + b) * (3 * CDIM) + CDIM + h * HD;
            double s = 0.0;
            #pragma unroll 8
            for (int d = 0; d < HD; d++) s += (double)q0s[d] * (double)kp[d];
            sc[t] = s * 0.125;
        }
        __syncthreads();
        if (t == 0) {
            double mx = sc[0];
            for (int j = 1; j < NTOK; j++) mx = fmax(mx, sc[j]);
            double sm = 0.0;
            for (int j = 0; j < NTOK; j++) sm += exp(sc[j] - mx);
            red[0] = mx; red[1] = sm;
        }
        __syncthreads();
        if (t >= 1 && t < NTOK)
            acc += exp(sc[t] - red[0]) / red[1];
    }
    if (t >= 1 && t < NTOK)
        cls[(size_t)b * NP + (t - 1)] = (float)(acc * (1.0 / NH));
}

// ---------------- exact stable top-k (value desc, index asc ties) -----------
__global__ void topk_kernel(const float* __restrict__ cls,
                            int* __restrict__ idx, int* __restrict__ comp)
{
    __shared__ float v[NP];
    const int b = blockIdx.x, t = threadIdx.x;
    if (t < NP) v[t] = cls[b * NP + t];
    __syncthreads();
    if (t < NP) {
        const float mv = v[t];
        int r = 0;
        for (int j = 0; j < NP; j++) {
            const float vj = v[j];
            r += (vj > mv) || (vj == mv && j < t);
        }
        if (r < LKEEP) idx[b * LKEEP + r] = t;
        else           comp[b * LKEEP + (r - LKEEP)] = t;
    }
}

// ---------------- build x_new: [cls, topk tokens (desc), fused token] -------
__global__ void gather_kernel(const float* __restrict__ xres,
                              const int* __restrict__ idx,
                              const int* __restrict__ comp,
                              const float* __restrict__ cls,
                              float* __restrict__ xnew)
{
    const int nn = blockIdx.x;   // 0..99
    const int b  = blockIdx.y;
    const int t  = threadIdx.x;  // 256 threads, 3 c's each
    float* dst = xnew + ((size_t)nn * BATCH + b) * CDIM;

    if (nn == 0) {
        const float* src = xres + (size_t)b * CDIM;  // token 0
        dst[t] = src[t]; dst[t + 256] = src[t + 256]; dst[t + 512] = src[t + 512];
    } else if (nn <= LKEEP) {
        const int tok = 1 + idx[b * LKEEP + (nn - 1)];
        const float* src = xres + ((size_t)tok * BATCH + b) * CDIM;
        dst[t] = src[t]; dst[t + 256] = src[t + 256]; dst[t + 512] = src[t + 512];
    } else {
        float a0 = 0.f, a1 = 0.f, a2 = 0.f;
        for (int q = 0; q < LKEEP; q++) {
            const int j = comp[b * LKEEP + q];
            const float w = cls[b * NP + j];
            const float* src = xres + ((size_t)(1 + j) * BATCH + b) * CDIM;
            a0 += src[t] * w; a1 += src[t + 256] * w; a2 += src[t + 512] * w;
        }
        dst[t] = a0; dst[t + 256] = a1; dst[t + 512] = a2;
    }
}

// ---------------- launch ----------------------------------------------------
extern "C" void kernel_launch(void* const* d_in, const int* in_sizes, int n_in,
                              void* d_out, int out_size)
{
    const float* x     = (const float*)d_in[0];
    const float* ln1_g = (const float*)d_in[1];
    const float* ln1_b = (const float*)d_in[2];
    const float* in_w  = (const float*)d_in[3];
    const float* in_b  = (const float*)d_in[4];
    const float* ow    = (const float*)d_in[5];
    const float* ob    = (const float*)d_in[6];
    const float* ln2_g = (const float*)d_in[7];
    const float* ln2_b = (const float*)d_in[8];
    const float* fc_w  = (const float*)d_in[9];
    const float* fc_b  = (const float*)d_in[10];
    const float* pj_w  = (const float*)d_in[11];
    const float* pj_b  = (const float*)d_in[12];
    float* out = (float*)d_out;

    float *ln1, *qkv, *att, *xres, *cls, *xnew, *ln2v, *fcv;
    int *idxp, *compp;
    cudaGetSymbolAddress((void**)&ln1,   g_ln1);
    cudaGetSymbolAddress((void**)&qkv,   g_qkv);
    cudaGetSymbolAddress((void**)&att,   g_att);
    cudaGetSymbolAddress((void**)&xres,  g_xres);
    cudaGetSymbolAddress((void**)&cls,   g_cls);
    cudaGetSymbolAddress((void**)&idxp,  g_idx);
    cudaGetSymbolAddress((void**)&compp, g_comp);
    cudaGetSymbolAddress((void**)&xnew,  g_xnew);
    cudaGetSymbolAddress((void**)&ln2v,  g_ln2);
    cudaGetSymbolAddress((void**)&fcv,   g_fc);

    cudaFuncSetAttribute(attn_kernel, cudaFuncAttributeMaxDynamicSharedMemorySize,
                         ATT_SMEM);

    // 1) ln1
    ln_kernel<<<M1, 256>>>(x, ln1_g, ln1_b, ln1);
    // 2) qkv = ln1 @ in_proj_w^T + b   (50432 x 2304, K=768)
    sgemm_kernel<<<dim3(3 * CDIM / 128, M1 / 128), 256>>>(
        ln1, in_w, in_b, nullptr, qkv, M1, 3 * CDIM, CDIM, 0);
    // 3) attention (per b,h)
    attn_kernel<<<dim3(BATCH, NH), 256, ATT_SMEM>>>(qkv, att);
    // 4) CLS-row attention in fp64 (exact ranking)
    cls_attn_kernel<<<BATCH, 256>>>(qkv, cls);
    // 5) out_proj + residual x  -> xres
    sgemm_kernel<<<dim3(CDIM / 128, M1 / 128), 256>>>(
        att, ow, ob, x, xres, M1, CDIM, CDIM, 0);
    // 6) top-k + complement
    topk_kernel<<<BATCH, 256>>>(cls, idxp, compp);
    // 7) build x_new (100, B, C)
    gather_kernel<<<dim3(NNEW, BATCH), 256>>>(xres, idxp, compp, cls, xnew);
    // 8) ln2
    ln_kernel<<<M2, 256>>>(xnew, ln2_g, ln2_b, ln2v);
    // 9) fc + quickgelu (25600 x 3072, K=768)
    sgemm_kernel<<<dim3(4 * CDIM / 128, M2 / 128), 256>>>(
        ln2v, fc_w, fc_b, nullptr, fcv, M2, 4 * CDIM, CDIM, 1);
    // 10) proj + residual x_new -> out (25600 x 768, K=3072)
    sgemm_kernel<<<dim3(CDIM / 128, M2 / 128), 256>>>(
        fcv, pj_w, pj_b, xnew, out, M2, CDIM, 4 * CDIM, 0);
}

// round 5
// speedup vs baseline: 1.3275x; 1.3275x over previous
#include <cuda_runtime.h>
#include <cuda_bf16.h>
#include <math.h>
#include <stdint.h>

#define NTOK  197
#define BATCH 256
#define CDIM  768
#define NH    12
#define HD    64
#define LKEEP 98
#define NP    (NTOK - 1)     // 196
#define NNEW  (LKEEP + 2)    // 100
#define M1    (NTOK * BATCH) // 50432
#define M2    (NNEW * BATCH) // 25600

typedef __nv_bfloat16  bf16;
typedef __nv_bfloat162 bf162;

// ---------------- scratch (device globals; no cudaMalloc allowed) ----------
__device__ float g_ln1 [(size_t)M1 * CDIM];          // fp32 (cls path)
__device__ float g_qkv [(size_t)M1 * 3 * CDIM];
__device__ float g_xres[(size_t)M1 * CDIM];
__device__ float g_cls [(size_t)BATCH * NP];
__device__ int   g_idx [BATCH * LKEEP];
__device__ int   g_comp[BATCH * LKEEP];
__device__ float g_xnew[(size_t)M2 * CDIM];

__device__ bf16 g_ln1h[(size_t)M1 * CDIM];
__device__ bf16 g_ln1l[(size_t)M1 * CDIM];
__device__ bf16 g_atth[(size_t)M1 * CDIM];
__device__ bf16 g_attl[(size_t)M1 * CDIM];
__device__ bf16 g_ln2h[(size_t)M2 * CDIM];
__device__ bf16 g_ln2l[(size_t)M2 * CDIM];
__device__ bf16 g_fch [(size_t)M2 * 4 * CDIM];
__device__ bf16 g_fcl [(size_t)M2 * 4 * CDIM];
// weights concatenated: in_w | out_w | fc_w | pj_w
#define O_INW 0
#define O_OW  (3 * CDIM * CDIM)                       // 1769472
#define O_FCW (O_OW + CDIM * CDIM)                    // 2359296
#define O_PJW (O_FCW + 4 * CDIM * CDIM)               // 4718592
#define W_TOT (O_PJW + 4 * CDIM * CDIM)               // 7077888
__device__ bf16 g_wh[W_TOT];
__device__ bf16 g_wl[W_TOT];

// ---------------- helpers ----------------------------------------------------
__device__ __forceinline__ uint32_t smem_u32(const void* p) {
    uint32_t a;
    asm("{ .reg .u64 t; cvta.to.shared.u64 t, %1; cvt.u32.u64 %0, t; }"
        : "=r"(a) : "l"(p));
    return a;
}
__device__ __forceinline__ void ldsm4(uint32_t r[4], uint32_t addr) {
    asm volatile("ldmatrix.sync.aligned.m8n8.x4.shared.b16 {%0,%1,%2,%3}, [%4];"
        : "=r"(r[0]), "=r"(r[1]), "=r"(r[2]), "=r"(r[3]) : "r"(addr));
}
__device__ __forceinline__ void ldsm2(uint32_t r[2], uint32_t addr) {
    asm volatile("ldmatrix.sync.aligned.m8n8.x2.shared.b16 {%0,%1}, [%2];"
        : "=r"(r[0]), "=r"(r[1]) : "r"(addr));
}
__device__ __forceinline__ void mma_bf16(float c[4], const uint32_t a[4],
                                         const uint32_t b[2]) {
    asm volatile("mma.sync.aligned.m16n8k16.row.col.f32.bf16.bf16.f32 "
        "{%0,%1,%2,%3}, {%4,%5,%6,%7}, {%8,%9}, {%0,%1,%2,%3};"
        : "+f"(c[0]), "+f"(c[1]), "+f"(c[2]), "+f"(c[3])
        : "r"(a[0]), "r"(a[1]), "r"(a[2]), "r"(a[3]), "r"(b[0]), "r"(b[1]));
}
__device__ __forceinline__ void split_bf16(float x, bf16& h, bf16& l) {
    h = __float2bfloat16(x);
    l = __float2bfloat16(x - __bfloat162float(h));
}

// ---------------- fp32 -> (hi, lo) bf16 converter ---------------------------
__global__ void convert_kernel(const float* __restrict__ s,
                               bf16* __restrict__ hi, bf16* __restrict__ lo,
                               int n4)
{
    const int i = blockIdx.x * 256 + threadIdx.x;
    if (i >= n4) return;
    float4 v = ((const float4*)s)[i];
    bf16 h0, h1, h2, h3, l0, l1, l2, l3;
    split_bf16(v.x, h0, l0); split_bf16(v.y, h1, l1);
    split_bf16(v.z, h2, l2); split_bf16(v.w, h3, l3);
    bf162 a, b;
    a.x = h0; a.y = h1; b.x = h2; b.y = h3;
    ((bf162*)hi)[2 * i] = a; ((bf162*)hi)[2 * i + 1] = b;
    a.x = l0; a.y = l1; b.x = l2; b.y = l3;
    ((bf162*)lo)[2 * i] = a; ((bf162*)lo)[2 * i + 1] = b;
}

// ---------------- layernorm: one block per row of 768 ----------------------
__global__ void ln_kernel(const float* __restrict__ x,
                          const float* __restrict__ gam,
                          const float* __restrict__ bet,
                          float* __restrict__ y,
                          bf16* __restrict__ yh, bf16* __restrict__ yl)
{
    const int row = blockIdx.x;
    const int t   = threadIdx.x;               // 256 threads, 3 elems each
    const float* xr = x + (size_t)row * CDIM;

    float v0 = xr[t], v1 = xr[t + 256], v2 = xr[t + 512];
    float s  = v0 + v1 + v2;
    float ss = v0 * v0 + v1 * v1 + v2 * v2;

    __shared__ float red[16];
    #pragma unroll
    for (int o = 16; o; o >>= 1) {
        s  += __shfl_xor_sync(0xffffffffu, s,  o);
        ss += __shfl_xor_sync(0xffffffffu, ss, o);
    }
    const int warp = t >> 5, lane = t & 31;
    if (lane == 0) { red[warp] = s; red[warp + 8] = ss; }
    __syncthreads();
    float S = 0.f, SS = 0.f;
    #pragma unroll
    for (int i = 0; i < 8; i++) { S += red[i]; SS += red[i + 8]; }

    const float mu  = S * (1.f / CDIM);
    const float var = SS * (1.f / CDIM) - mu * mu;
    const float inv = rsqrtf(var + 1e-5f);

    const size_t base = (size_t)row * CDIM;
    #pragma unroll
    for (int e = 0; e < 3; e++) {
        const int c = t + e * 256;
        const float v = (e == 0 ? v0 : (e == 1 ? v1 : v2));
        const float o = (v - mu) * inv * gam[c] + bet[c];
        if (y) y[base + c] = o;
        bf16 h, l; split_bf16(o, h, l);
        yh[base + c] = h; yl[base + c] = l;
    }
}

// ---------------- bf16x3 mma.sync GEMM ------------------------------------
// C[M,N] = A[M,K] @ W[N,K]^T + bias (+act) (+res). Output fp32 (Cf) or
// split hi/lo bf16 (Ch, Cl). A and W supplied as pre-split bf16 hi/lo.
// 128x128 CTA tile, 8 warps in 2(m) x 4(n), warp tile 64x32,
// m16n8k16 mma, K-chunk 32, double-buffered smem with register prefetch.
#define ROWB   80                    // smem bytes per row: 32 bf16 + 8 pad
#define TBYTES (128 * ROWB)          // 10240 per operand tensor
#define STG    (4 * TBYTES)          // 40960 per stage
#define GSM    (2 * STG)             // 81920 total

__global__ void __launch_bounds__(256)
bf16_gemm_kernel(const bf16* __restrict__ Ah, const bf16* __restrict__ Al,
                 const bf16* __restrict__ Wh, const bf16* __restrict__ Wl,
                 const float* __restrict__ bias, const float* __restrict__ res,
                 float* __restrict__ Cf, bf16* __restrict__ Ch,
                 bf16* __restrict__ Cl, int M, int Nn, int K, int act)
{
    extern __shared__ char dsm[];
    const uint32_t sb = smem_u32(dsm);

    const int tid = threadIdx.x, lane = tid & 31, wid = tid >> 5;
    const int wm = wid >> 2, wn = wid & 3;     // 2 x 4 warp grid
    const int m0 = blockIdx.y * 128, n0 = blockIdx.x * 128;

    float acc[4][4][4] = {};

    // staging coords (shared by loads and stores)
    const int srow = 0; (void)srow;

    // preload chunk 0
    #pragma unroll
    for (int r = 0; r < 4; r++) {
        const int idx = tid + (r << 8);
        const int row = idx >> 3, c4 = idx & 7;
        const size_t ga = (size_t)(m0 + row) * K + c4 * 4;
        const size_t gw = (size_t)(n0 + row) * K + c4 * 4;
        const int off = row * ROWB + c4 * 8;
        *(uint2*)(dsm + off)               = *(const uint2*)(Ah + ga);
        *(uint2*)(dsm + TBYTES + off)      = *(const uint2*)(Al + ga);
        *(uint2*)(dsm + 2 * TBYTES + off)  = *(const uint2*)(Wh + gw);
        *(uint2*)(dsm + 3 * TBYTES + off)  = *(const uint2*)(Wl + gw);
    }
    __syncthreads();

    const int nch = K >> 5;
    for (int t = 0; t < nch; t++) {
        const int s = t & 1;
        uint2 pa_h[4], pa_l[4], pw_h[4], pw_l[4];
        if (t + 1 < nch) {
            const int k0 = (t + 1) << 5;
            #pragma unroll
            for (int r = 0; r < 4; r++) {
                const int idx = tid + (r << 8);
                const int row = idx >> 3, c4 = idx & 7;
                const size_t ga = (size_t)(m0 + row) * K + k0 + c4 * 4;
                const size_t gw = (size_t)(n0 + row) * K + k0 + c4 * 4;
                pa_h[r] = *(const uint2*)(Ah + ga);
                pa_l[r] = *(const uint2*)(Al + ga);
                pw_h[r] = *(const uint2*)(Wh + gw);
                pw_l[r] = *(const uint2*)(Wl + gw);
            }
        }

        // compute on buffer s
        const uint32_t sA = sb + s * STG;
        #pragma unroll
        for (int ks = 0; ks < 2; ks++) {
            uint32_t ah[4][4], al[4][4];
            #pragma unroll
            for (int mf = 0; mf < 4; mf++) {
                const uint32_t ra = sA +
                    (uint32_t)((wm * 64 + mf * 16 + (lane & 15)) * ROWB
                               + ks * 32 + ((lane >> 4) << 4));
                ldsm4(ah[mf], ra);
                ldsm4(al[mf], ra + TBYTES);
            }
            #pragma unroll
            for (int nf = 0; nf < 4; nf++) {
                const uint32_t rb = sA + 2 * TBYTES +
                    (uint32_t)((wn * 32 + nf * 8 + (lane & 7)) * ROWB
                               + ks * 32 + (((lane >> 3) & 1) << 4));
                uint32_t bh[2], bl[2];
                ldsm2(bh, rb);
                ldsm2(bl, rb + TBYTES);
                #pragma unroll
                for (int mf = 0; mf < 4; mf++) {
                    mma_bf16(acc[mf][nf], ah[mf], bh);
                    mma_bf16(acc[mf][nf], ah[mf], bl);
                    mma_bf16(acc[mf][nf], al[mf], bh);
                }
            }
        }

        if (t + 1 < nch) {
            char* d = dsm + (s ^ 1) * STG;
            #pragma unroll
            for (int r = 0; r < 4; r++) {
                const int idx = tid + (r << 8);
                const int row = idx >> 3, c4 = idx & 7;
                const int off = row * ROWB + c4 * 8;
                *(uint2*)(d + off)              = pa_h[r];
                *(uint2*)(d + TBYTES + off)     = pa_l[r];
                *(uint2*)(d + 2 * TBYTES + off) = pw_h[r];
                *(uint2*)(d + 3 * TBYTES + off) = pw_l[r];
            }
        }
        __syncthreads();
    }

    // epilogue
    #pragma unroll
    for (int mf = 0; mf < 4; mf++) {
        #pragma unroll
        for (int nf = 0; nf < 4; nf++) {
            const int rr = m0 + wm * 64 + mf * 16 + (lane >> 2);
            const int cc = n0 + wn * 32 + nf * 8 + ((lane & 3) << 1);
            const float b0 = bias[cc], b1 = bias[cc + 1];
            float v0 = acc[mf][nf][0] + b0;
            float v1 = acc[mf][nf][1] + b1;
            float v2 = acc[mf][nf][2] + b0;
            float v3 = acc[mf][nf][3] + b1;
            if (act) {
                v0 = v0 / (1.f + __expf(-1.702f * v0));
                v1 = v1 / (1.f + __expf(-1.702f * v1));
                v2 = v2 / (1.f + __expf(-1.702f * v2));
                v3 = v3 / (1.f + __expf(-1.702f * v3));
            }
            const size_t o0 = (size_t)rr * Nn + cc;
            const size_t o1 = (size_t)(rr + 8) * Nn + cc;
            if (Cf) {
                if (res) {
                    float2 r0 = *(const float2*)(res + o0);
                    float2 r1 = *(const float2*)(res + o1);
                    v0 += r0.x; v1 += r0.y; v2 += r1.x; v3 += r1.y;
                }
                float2 s0; s0.x = v0; s0.y = v1;
                float2 s1; s1.x = v2; s1.y = v3;
                *(float2*)(Cf + o0) = s0;
                *(float2*)(Cf + o1) = s1;
            } else {
                bf16 h, l; bf162 hh, ll;
                split_bf16(v0, h, l); hh.x = h; ll.x = l;
                split_bf16(v1, h, l); hh.y = h; ll.y = l;
                *(bf162*)(Ch + o0) = hh; *(bf162*)(Cl + o0) = ll;
                split_bf16(v2, h, l); hh.x = h; ll.x = l;
                split_bf16(v3, h, l); hh.y = h; ll.y = l;
                *(bf162*)(Ch + o1) = hh; *(bf162*)(Cl + o1) = ll;
            }
        }
    }
}

// ---------------- attention: one CTA per (b,h), K/V resident in smem -------
#define KVPAD 65
#define ATT_SMEM ((2 * NTOK * KVPAD + 8 * NTOK + 8 * HD) * (int)sizeof(float))

__global__ void __launch_bounds__(256)
attn_kernel(const float* __restrict__ qkv,
            bf16* __restrict__ outh, bf16* __restrict__ outl)
{
    extern __shared__ float sm[];
    float* Ks = sm;                       // [NTOK][65]
    float* Vs = Ks + NTOK * KVPAD;        // [NTOK][65]
    float* Ps = Vs + NTOK * KVPAD;        // [8][NTOK]
    float* Qs = Ps + 8 * NTOK;            // [8][64]

    const int b = blockIdx.x, h = blockIdx.y;
    const int tid = threadIdx.x, lane = tid & 31, warp = tid >> 5;

    for (int idx = tid; idx < NTOK * HD; idx += 256) {
        const int j = idx >> 6, d = idx & 63;
        const size_t g = ((size_t)j * BATCH + b) * (3 * CDIM) + h * HD + d;
        Ks[j * KVPAD + d] = qkv[g + CDIM];
        Vs[j * KVPAD + d] = qkv[g + 2 * CDIM];
    }
    __syncthreads();

    for (int i = warp; i < NTOK; i += 8) {
        const size_t qg = ((size_t)i * BATCH + b) * (3 * CDIM) + h * HD;
        Qs[warp * HD + lane]      = qkv[qg + lane];
        Qs[warp * HD + lane + 32] = qkv[qg + lane + 32];
        __syncwarp();

        float s[7];
        #pragma unroll
        for (int t = 0; t < 7; t++) s[t] = 0.f;
        #pragma unroll 8
        for (int d = 0; d < HD; d++) {
            const float qd = Qs[warp * HD + d];
            #pragma unroll
            for (int t = 0; t < 7; t++) {
                const int j = lane + t * 32;
                if (j < NTOK) s[t] += qd * Ks[j * KVPAD + d];
            }
        }
        float mx = -1e30f;
        #pragma unroll
        for (int t = 0; t < 7; t++) {
            const int j = lane + t * 32;
            s[t] = (j < NTOK) ? s[t] * 0.125f : -1e30f;
            mx = fmaxf(mx, s[t]);
        }
        #pragma unroll
        for (int o = 16; o; o >>= 1) mx = fmaxf(mx, __shfl_xor_sync(0xffffffffu, mx, o));
        float sum = 0.f;
        #pragma unroll
        for (int t = 0; t < 7; t++) {
            const int j = lane + t * 32;
            const float e = (j < NTOK) ? __expf(s[t] - mx) : 0.f;
            s[t] = e; sum += e;
        }
        #pragma unroll
        for (int o = 16; o; o >>= 1) sum += __shfl_xor_sync(0xffffffffu, sum, o);
        const float inv = 1.f / sum;
        #pragma unroll
        for (int t = 0; t < 7; t++) {
            const int j = lane + t * 32;
            if (j < NTOK) Ps[warp * NTOK + j] = s[t] * inv;
        }
        __syncwarp();

        float a0 = 0.f, a1 = 0.f;
        #pragma unroll 4
        for (int j = 0; j < NTOK; j++) {
            const float p = Ps[warp * NTOK + j];
            a0 += p * Vs[j * KVPAD + lane];
            a1 += p * Vs[j * KVPAD + lane + 32];
        }
        const size_t og = ((size_t)i * BATCH + b) * CDIM + h * HD;
        bf16 hh, ll;
        split_bf16(a0, hh, ll);
        outh[og + lane] = hh;      outl[og + lane] = ll;
        split_bf16(a1, hh, ll);
        outh[og + lane + 32] = hh; outl[og + lane + 32] = ll;
        __syncwarp();
    }
}

// ---------------- CLS scores in fp64 straight from ln1 + weights ------------
// s_j = ln1_j . (Wk^T q0) + q0.bk ; q0 = Wq ln1_0 + bq. GEMM-noise-free ranking.
__global__ void __launch_bounds__(256)
cls_score_kernel(const float* __restrict__ ln1, const float* __restrict__ inw,
                 const float* __restrict__ inb, float* __restrict__ cls)
{
    const int b = blockIdx.x, tid = threadIdx.x;
    const int lane = tid & 31, w = tid >> 5;
    __shared__ float  ln0[CDIM];
    __shared__ double q0[HD];
    __shared__ double wv[CDIM];
    __shared__ double sj[NTOK];
    __shared__ double redd[8];
    __shared__ double beta_s;

    for (int c = tid; c < CDIM; c += 256)
        ln0[c] = ln1[(size_t)b * CDIM + c];
    __syncthreads();

    double acc = 0.0;
    for (int h = 0; h < NH; h++) {
        {
            const int d = tid >> 2, part = tid & 3;
            const float* wr = inw + (size_t)(h * HD + d) * CDIM;
            double s = 0.0;
            const int c0 = part * 192;
            for (int c = c0; c < c0 + 192; c++)
                s += (double)ln0[c] * (double)wr[c];
            s += __shfl_xor_sync(0xffffffffu, s, 1);
            s += __shfl_xor_sync(0xffffffffu, s, 2);
            if (part == 0) q0[d] = s + (double)inb[h * HD + d];
        }
        __syncthreads();
        for (int c = tid; c < CDIM; c += 256) {
            double s = 0.0;
            #pragma unroll 8
            for (int d = 0; d < HD; d++)
                s += q0[d] * (double)inw[(size_t)(CDIM + h * HD + d) * CDIM + c];
            wv[c] = s;
        }
        if (tid == 0) {
            double bsum = 0.0;
            for (int d = 0; d < HD; d++)
                bsum += q0[d] * (double)inb[CDIM + h * HD + d];
            beta_s = bsum;
        }
        __syncthreads();
        for (int j = w; j < NTOK; j += 8) {
            const float* xr = ln1 + ((size_t)j * BATCH + b) * CDIM;
            double s = 0.0;
            for (int c = lane; c < CDIM; c += 32)
                s += (double)xr[c] * wv[c];
            #pragma unroll
            for (int o = 16; o; o >>= 1) s += __shfl_xor_sync(0xffffffffu, s, o);
            if (lane == 0) sj[j] = (s + beta_s) * 0.125;
        }
        __syncthreads();
        double v = (tid < NTOK) ? sj[tid] : -1e300;
        #pragma unroll
        for (int o = 16; o; o >>= 1) v = fmax(v, __shfl_xor_sync(0xffffffffu, v, o));
        if (lane == 0) redd[w] = v;
        __syncthreads();
        double mx = redd[0];
        #pragma unroll
        for (int i = 1; i < 8; i++) mx = fmax(mx, redd[i]);
        const double e = (tid < NTOK) ? exp(sj[tid] - mx) : 0.0;
        double sv = e;
        #pragma unroll
        for (int o = 16; o; o >>= 1) sv += __shfl_xor_sync(0xffffffffu, sv, o);
        __syncthreads();
        if (lane == 0) redd[w] = sv;
        __syncthreads();
        double S = 0.0;
        #pragma unroll
        for (int i = 0; i < 8; i++) S += redd[i];
        if (tid >= 1 && tid < NTOK) acc += e / S;
        __syncthreads();
    }
    if (tid >= 1 && tid < NTOK)
        cls[(size_t)b * NP + (tid - 1)] = (float)(acc * (1.0 / NH));
}

// ---------------- exact stable top-k (value desc, index asc ties) -----------
__global__ void topk_kernel(const float* __restrict__ cls,
                            int* __restrict__ idx, int* __restrict__ comp)
{
    __shared__ float v[NP];
    const int b = blockIdx.x, t = threadIdx.x;
    if (t < NP) v[t] = cls[b * NP + t];
    __syncthreads();
    if (t < NP) {
        const float mv = v[t];
        int r = 0;
        for (int j = 0; j < NP; j++) {
            const float vj = v[j];
            r += (vj > mv) || (vj == mv && j < t);
        }
        if (r < LKEEP) idx[b * LKEEP + r] = t;
        else           comp[b * LKEEP + (r - LKEEP)] = t;
    }
}

// ---------------- build x_new: [cls, topk tokens (desc), fused token] -------
__global__ void gather_kernel(const float* __restrict__ xres,
                              const int* __restrict__ idx,
                              const int* __restrict__ comp,
                              const float* __restrict__ cls,
                              float* __restrict__ xnew)
{
    const int nn = blockIdx.x;   // 0..99
    const int b  = blockIdx.y;
    const int t  = threadIdx.x;  // 256 threads, 3 c's each
    float* dst = xnew + ((size_t)nn * BATCH + b) * CDIM;

    if (nn == 0) {
        const float* src = xres + (size_t)b * CDIM;
        dst[t] = src[t]; dst[t + 256] = src[t + 256]; dst[t + 512] = src[t + 512];
    } else if (nn <= LKEEP) {
        const int tok = 1 + idx[b * LKEEP + (nn - 1)];
        const float* src = xres + ((size_t)tok * BATCH + b) * CDIM;
        dst[t] = src[t]; dst[t + 256] = src[t + 256]; dst[t + 512] = src[t + 512];
    } else {
        float a0 = 0.f, a1 = 0.f, a2 = 0.f;
        for (int q = 0; q < LKEEP; q++) {
            const int j = comp[b * LKEEP + q];
            const float w = cls[b * NP + j];
            const float* src = xres + ((size_t)(1 + j) * BATCH + b) * CDIM;
            a0 += src[t] * w; a1 += src[t + 256] * w; a2 += src[t + 512] * w;
        }
        dst[t] = a0; dst[t + 256] = a1; dst[t + 512] = a2;
    }
}

// ---------------- launch ----------------------------------------------------
extern "C" void kernel_launch(void* const* d_in, const int* in_sizes, int n_in,
                              void* d_out, int out_size)
{
    const float* x     = (const float*)d_in[0];
    const float* ln1_g = (const float*)d_in[1];
    const float* ln1_b = (const float*)d_in[2];
    const float* in_w  = (const float*)d_in[3];
    const float* in_b  = (const float*)d_in[4];
    const float* ow    = (const float*)d_in[5];
    const float* ob    = (const float*)d_in[6];
    const float* ln2_g = (const float*)d_in[7];
    const float* ln2_b = (const float*)d_in[8];
    const float* fc_w  = (const float*)d_in[9];
    const float* fc_b  = (const float*)d_in[10];
    const float* pj_w  = (const float*)d_in[11];
    const float* pj_b  = (const float*)d_in[12];
    float* out = (float*)d_out;

    float *ln1, *qkv, *xres, *cls, *xnew;
    int *idxp, *compp;
    bf16 *ln1h, *ln1l, *atth, *attl, *ln2h, *ln2l, *fch, *fcl, *wh, *wl;
    cudaGetSymbolAddress((void**)&ln1,   g_ln1);
    cudaGetSymbolAddress((void**)&qkv,   g_qkv);
    cudaGetSymbolAddress((void**)&xres,  g_xres);
    cudaGetSymbolAddress((void**)&cls,   g_cls);
    cudaGetSymbolAddress((void**)&idxp,  g_idx);
    cudaGetSymbolAddress((void**)&compp, g_comp);
    cudaGetSymbolAddress((void**)&xnew,  g_xnew);
    cudaGetSymbolAddress((void**)&ln1h,  g_ln1h);
    cudaGetSymbolAddress((void**)&ln1l,  g_ln1l);
    cudaGetSymbolAddress((void**)&atth,  g_atth);
    cudaGetSymbolAddress((void**)&attl,  g_attl);
    cudaGetSymbolAddress((void**)&ln2h,  g_ln2h);
    cudaGetSymbolAddress((void**)&ln2l,  g_ln2l);
    cudaGetSymbolAddress((void**)&fch,   g_fch);
    cudaGetSymbolAddress((void**)&fcl,   g_fcl);
    cudaGetSymbolAddress((void**)&wh,    g_wh);
    cudaGetSymbolAddress((void**)&wl,    g_wl);

    cudaFuncSetAttribute(attn_kernel, cudaFuncAttributeMaxDynamicSharedMemorySize,
                         ATT_SMEM);
    cudaFuncSetAttribute(bf16_gemm_kernel, cudaFuncAttributeMaxDynamicSharedMemorySize,
                         GSM);

    // 0) split weights into bf16 hi/lo
    convert_kernel<<<(3 * CDIM * CDIM / 4 + 255) / 256, 256>>>(
        in_w, wh + O_INW, wl + O_INW, 3 * CDIM * CDIM / 4);
    convert_kernel<<<(CDIM * CDIM / 4 + 255) / 256, 256>>>(
        ow, wh + O_OW, wl + O_OW, CDIM * CDIM / 4);
    convert_kernel<<<(4 * CDIM * CDIM / 4 + 255) / 256, 256>>>(
        fc_w, wh + O_FCW, wl + O_FCW, 4 * CDIM * CDIM / 4);
    convert_kernel<<<(4 * CDIM * CDIM / 4 + 255) / 256, 256>>>(
        pj_w, wh + O_PJW, wl + O_PJW, 4 * CDIM * CDIM / 4);

    // 1) ln1 (fp32 for cls path + hi/lo for GEMM)
    ln_kernel<<<M1, 256>>>(x, ln1_g, ln1_b, ln1, ln1h, ln1l);
    // 2) qkv = ln1 @ in_proj_w^T + b   (50432 x 2304, K=768) -> fp32
    bf16_gemm_kernel<<<dim3(3 * CDIM / 128, M1 / 128), 256, GSM>>>(
        ln1h, ln1l, wh + O_INW, wl + O_INW, in_b, nullptr,
        qkv, nullptr, nullptr, M1, 3 * CDIM, CDIM, 0);
    // 3) attention (per b,h) -> att hi/lo
    attn_kernel<<<dim3(BATCH, NH), 256, ATT_SMEM>>>(qkv, atth, attl);
    // 4) CLS scores in fp64 from ln1 (exact, GEMM-independent ranking)
    cls_score_kernel<<<BATCH, 256>>>(ln1, in_w, in_b, cls);
    // 5) out_proj + residual x -> xres (fp32)
    bf16_gemm_kernel<<<dim3(CDIM / 128, M1 / 128), 256, GSM>>>(
        atth, attl, wh + O_OW, wl + O_OW, ob, x,
        xres, nullptr, nullptr, M1, CDIM, CDIM, 0);
    // 6) top-k + complement
    topk_kernel<<<BATCH, 256>>>(cls, idxp, compp);
    // 7) build x_new (100, B, C)
    gather_kernel<<<dim3(NNEW, BATCH), 256>>>(xres, idxp, compp, cls, xnew);
    // 8) ln2 -> hi/lo only
    ln_kernel<<<M2, 256>>>(xnew, ln2_g, ln2_b, nullptr, ln2h, ln2l);
    // 9) fc + quickgelu (25600 x 3072, K=768) -> hi/lo bf16
    bf16_gemm_kernel<<<dim3(4 * CDIM / 128, M2 / 128), 256, GSM>>>(
        ln2h, ln2l, wh + O_FCW, wl + O_FCW, fc_b, nullptr,
        nullptr, fch, fcl, M2, 4 * CDIM, CDIM, 1);
    // 10) proj + residual x_new -> out (25600 x 768, K=3072)
    bf16_gemm_kernel<<<dim3(CDIM / 128, M2 / 128), 256, GSM>>>(
        fch, fcl, wh + O_PJW, wl + O_PJW, pj_b, xnew,
        out, nullptr, nullptr, M2, CDIM, 4 * CDIM, 0);
}

// round 6
// speedup vs baseline: 1.4423x; 1.0865x over previous
#include <cuda_runtime.h>
#include <cuda_bf16.h>
#include <math.h>
#include <stdint.h>

#define NTOK  197
#define BATCH 256
#define CDIM  768
#define NH    12
#define HD    64
#define LKEEP 98
#define NP    (NTOK - 1)     // 196
#define NNEW  (LKEEP + 2)    // 100
#define M1    (NTOK * BATCH) // 50432
#define M2    (NNEW * BATCH) // 25600

typedef __nv_bfloat16  bf16;
typedef __nv_bfloat162 bf162;

// ---------------- scratch (device globals; no cudaMalloc allowed) ----------
__device__ float g_ln1 [(size_t)M1 * CDIM];          // fp32 (cls path)
__device__ float g_qkv [(size_t)M1 * 3 * CDIM];
__device__ float g_xres[(size_t)M1 * CDIM];
__device__ float g_cls [(size_t)BATCH * NP];
__device__ int   g_idx [BATCH * LKEEP];
__device__ int   g_comp[BATCH * LKEEP];
__device__ float g_xnew[(size_t)M2 * CDIM];

__device__ bf16 g_ln1h[(size_t)M1 * CDIM];
__device__ bf16 g_ln1l[(size_t)M1 * CDIM];
__device__ bf16 g_atth[(size_t)M1 * CDIM];
__device__ bf16 g_attl[(size_t)M1 * CDIM];
__device__ bf16 g_ln2h[(size_t)M2 * CDIM];
__device__ bf16 g_ln2l[(size_t)M2 * CDIM];
__device__ bf16 g_fch [(size_t)M2 * 4 * CDIM];
__device__ bf16 g_fcl [(size_t)M2 * 4 * CDIM];
// weights concatenated: in_w | out_w | fc_w | pj_w
#define O_INW 0
#define O_OW  (3 * CDIM * CDIM)
#define O_FCW (O_OW + CDIM * CDIM)
#define O_PJW (O_FCW + 4 * CDIM * CDIM)
#define W_TOT (O_PJW + 4 * CDIM * CDIM)
__device__ bf16 g_wh[W_TOT];
__device__ bf16 g_wl[W_TOT];

// ---------------- helpers ----------------------------------------------------
__device__ __forceinline__ uint32_t smem_u32(const void* p) {
    uint32_t a;
    asm("{ .reg .u64 t; cvta.to.shared.u64 t, %1; cvt.u32.u64 %0, t; }"
        : "=r"(a) : "l"(p));
    return a;
}
__device__ __forceinline__ void ldsm4(uint32_t r[4], uint32_t addr) {
    asm volatile("ldmatrix.sync.aligned.m8n8.x4.shared.b16 {%0,%1,%2,%3}, [%4];"
        : "=r"(r[0]), "=r"(r[1]), "=r"(r[2]), "=r"(r[3]) : "r"(addr));
}
__device__ __forceinline__ void ldsm2(uint32_t r[2], uint32_t addr) {
    asm volatile("ldmatrix.sync.aligned.m8n8.x2.shared.b16 {%0,%1}, [%2];"
        : "=r"(r[0]), "=r"(r[1]) : "r"(addr));
}
__device__ __forceinline__ void mma_bf16(float c[4], const uint32_t a[4],
                                         const uint32_t b[2]) {
    asm volatile("mma.sync.aligned.m16n8k16.row.col.f32.bf16.bf16.f32 "
        "{%0,%1,%2,%3}, {%4,%5,%6,%7}, {%8,%9}, {%0,%1,%2,%3};"
        : "+f"(c[0]), "+f"(c[1]), "+f"(c[2]), "+f"(c[3])
        : "r"(a[0]), "r"(a[1]), "r"(a[2]), "r"(a[3]), "r"(b[0]), "r"(b[1]));
}
__device__ __forceinline__ void split_bf16(float x, bf16& h, bf16& l) {
    h = __float2bfloat16(x);
    l = __float2bfloat16(x - __bfloat162float(h));
}
__device__ __forceinline__ void cp16(uint32_t dst, const void* src) {
    asm volatile("cp.async.cg.shared.global [%0], [%1], 16;"
                 :: "r"(dst), "l"(src));
}

// ---------------- fp32 -> (hi, lo) bf16 converter ---------------------------
__global__ void convert_kernel(const float* __restrict__ s,
                               bf16* __restrict__ hi, bf16* __restrict__ lo,
                               int n4)
{
    const int i = blockIdx.x * 256 + threadIdx.x;
    if (i >= n4) return;
    float4 v = ((const float4*)s)[i];
    bf16 h0, h1, h2, h3, l0, l1, l2, l3;
    split_bf16(v.x, h0, l0); split_bf16(v.y, h1, l1);
    split_bf16(v.z, h2, l2); split_bf16(v.w, h3, l3);
    bf162 a, b;
    a.x = h0; a.y = h1; b.x = h2; b.y = h3;
    ((bf162*)hi)[2 * i] = a; ((bf162*)hi)[2 * i + 1] = b;
    a.x = l0; a.y = l1; b.x = l2; b.y = l3;
    ((bf162*)lo)[2 * i] = a; ((bf162*)lo)[2 * i + 1] = b;
}

// ---------------- layernorm: one block per row of 768 ----------------------
__global__ void ln_kernel(const float* __restrict__ x,
                          const float* __restrict__ gam,
                          const float* __restrict__ bet,
                          float* __restrict__ y,
                          bf16* __restrict__ yh, bf16* __restrict__ yl)
{
    const int row = blockIdx.x;
    const int t   = threadIdx.x;
    const float* xr = x + (size_t)row * CDIM;

    float v0 = xr[t], v1 = xr[t + 256], v2 = xr[t + 512];
    float s  = v0 + v1 + v2;
    float ss = v0 * v0 + v1 * v1 + v2 * v2;

    __shared__ float red[16];
    #pragma unroll
    for (int o = 16; o; o >>= 1) {
        s  += __shfl_xor_sync(0xffffffffu, s,  o);
        ss += __shfl_xor_sync(0xffffffffu, ss, o);
    }
    const int warp = t >> 5, lane = t & 31;
    if (lane == 0) { red[warp] = s; red[warp + 8] = ss; }
    __syncthreads();
    float S = 0.f, SS = 0.f;
    #pragma unroll
    for (int i = 0; i < 8; i++) { S += red[i]; SS += red[i + 8]; }

    const float mu  = S * (1.f / CDIM);
    const float var = SS * (1.f / CDIM) - mu * mu;
    const float inv = rsqrtf(var + 1e-5f);

    const size_t base = (size_t)row * CDIM;
    #pragma unroll
    for (int e = 0; e < 3; e++) {
        const int c = t + e * 256;
        const float v = (e == 0 ? v0 : (e == 1 ? v1 : v2));
        const float o = (v - mu) * inv * gam[c] + bet[c];
        if (y) y[base + c] = o;
        bf16 h, l; split_bf16(o, h, l);
        yh[base + c] = h; yl[base + c] = l;
    }
}

// ---------------- bf16x3 mma.sync GEMM, cp.async 3-stage pipeline -----------
// C[M,N] = A[M,K] @ W[N,K]^T + bias (+act) (+res). A,W pre-split bf16 hi/lo.
// 128x128 CTA tile, 8 warps (2m x 4n), warp tile 64x32, K-chunk 32.
#define ROWB   80                    // smem bytes per row: 32 bf16 + 8 pad
#define TBYTES (128 * ROWB)          // 10240 per operand tensor
#define STG    (4 * TBYTES)          // 40960 per stage
#define GSM    (3 * STG)             // 122880 total (3 stages)

__global__ void __launch_bounds__(256)
bf16_gemm_kernel(const bf16* __restrict__ Ah, const bf16* __restrict__ Al,
                 const bf16* __restrict__ Wh, const bf16* __restrict__ Wl,
                 const float* __restrict__ bias, const float* __restrict__ res,
                 float* __restrict__ Cf, bf16* __restrict__ Ch,
                 bf16* __restrict__ Cl, int M, int Nn, int K, int act)
{
    extern __shared__ char dsm[];
    const uint32_t sb = smem_u32(dsm);

    const int tid = threadIdx.x, lane = tid & 31, wid = tid >> 5;
    const int wm = wid >> 2, wn = wid & 3;
    const int m0 = blockIdx.y * 128, n0 = blockIdx.x * 128;

    float acc[4][4][4] = {};

    auto issue = [&](int s, int t) {
        const int k0 = t << 5;
        #pragma unroll
        for (int r = 0; r < 8; r++) {
            const int id = tid + (r << 8);           // 0..2047
            const int tensor = id >> 9;              // 0..3
            const int w = id & 511;
            const int row = w >> 2, c4 = w & 3;      // 16B unit within 64B row
            const bf16* src;
            if      (tensor == 0) src = Ah + (size_t)(m0 + row) * K + k0 + c4 * 8;
            else if (tensor == 1) src = Al + (size_t)(m0 + row) * K + k0 + c4 * 8;
            else if (tensor == 2) src = Wh + (size_t)(n0 + row) * K + k0 + c4 * 8;
            else                  src = Wl + (size_t)(n0 + row) * K + k0 + c4 * 8;
            const uint32_t dst = sb + (uint32_t)(s * STG + tensor * TBYTES
                                                 + row * ROWB + c4 * 16);
            cp16(dst, src);
        }
        asm volatile("cp.async.commit_group;" ::: "memory");
    };

    const int nch = K >> 5;
    issue(0, 0);
    issue(1, 1);

    for (int t = 0; t < nch; t++) {
        const int s = t % 3;
        asm volatile("cp.async.wait_group 1;" ::: "memory");
        __syncthreads();
        if (t + 2 < nch) issue((t + 2) % 3, t + 2);
        else asm volatile("cp.async.commit_group;" ::: "memory");

        const uint32_t sA = sb + s * STG;
        #pragma unroll
        for (int ks = 0; ks < 2; ks++) {
            uint32_t ah[4][4], al[4][4];
            #pragma unroll
            for (int mf = 0; mf < 4; mf++) {
                const uint32_t ra = sA +
                    (uint32_t)((wm * 64 + mf * 16 + (lane & 15)) * ROWB
                               + ks * 32 + ((lane >> 4) << 4));
                ldsm4(ah[mf], ra);
                ldsm4(al[mf], ra + TBYTES);
            }
            #pragma unroll
            for (int nf = 0; nf < 4; nf++) {
                const uint32_t rb = sA + 2 * TBYTES +
                    (uint32_t)((wn * 32 + nf * 8 + (lane & 7)) * ROWB
                               + ks * 32 + (((lane >> 3) & 1) << 4));
                uint32_t bh[2], bl[2];
                ldsm2(bh, rb);
                ldsm2(bl, rb + TBYTES);
                #pragma unroll
                for (int mf = 0; mf < 4; mf++) {
                    mma_bf16(acc[mf][nf], ah[mf], bh);
                    mma_bf16(acc[mf][nf], ah[mf], bl);
                    mma_bf16(acc[mf][nf], al[mf], bh);
                }
            }
        }
        __syncthreads();
    }

    // epilogue
    #pragma unroll
    for (int mf = 0; mf < 4; mf++) {
        #pragma unroll
        for (int nf = 0; nf < 4; nf++) {
            const int rr = m0 + wm * 64 + mf * 16 + (lane >> 2);
            const int cc = n0 + wn * 32 + nf * 8 + ((lane & 3) << 1);
            const float b0 = bias[cc], b1 = bias[cc + 1];
            float v0 = acc[mf][nf][0] + b0;
            float v1 = acc[mf][nf][1] + b1;
            float v2 = acc[mf][nf][2] + b0;
            float v3 = acc[mf][nf][3] + b1;
            if (act) {
                v0 = v0 / (1.f + __expf(-1.702f * v0));
                v1 = v1 / (1.f + __expf(-1.702f * v1));
                v2 = v2 / (1.f + __expf(-1.702f * v2));
                v3 = v3 / (1.f + __expf(-1.702f * v3));
            }
            const size_t o0 = (size_t)rr * Nn + cc;
            const size_t o1 = (size_t)(rr + 8) * Nn + cc;
            if (Cf) {
                if (res) {
                    float2 r0 = *(const float2*)(res + o0);
                    float2 r1 = *(const float2*)(res + o1);
                    v0 += r0.x; v1 += r0.y; v2 += r1.x; v3 += r1.y;
                }
                float2 s0; s0.x = v0; s0.y = v1;
                float2 s1; s1.x = v2; s1.y = v3;
                *(float2*)(Cf + o0) = s0;
                *(float2*)(Cf + o1) = s1;
            } else {
                bf16 h, l; bf162 hh, ll;
                split_bf16(v0, h, l); hh.x = h; ll.x = l;
                split_bf16(v1, h, l); hh.y = h; ll.y = l;
                *(bf162*)(Ch + o0) = hh; *(bf162*)(Cl + o0) = ll;
                split_bf16(v2, h, l); hh.x = h; ll.x = l;
                split_bf16(v3, h, l); hh.y = h; ll.y = l;
                *(bf162*)(Ch + o1) = hh; *(bf162*)(Cl + o1) = ll;
            }
        }
    }
}

// ---------------- attention: 4 queries per warp pass, P via shuffle ---------
#define KVPAD 65
#define ATT_SMEM ((2 * NTOK * KVPAD + 8 * 4 * HD) * (int)sizeof(float))

__global__ void __launch_bounds__(256)
attn_kernel(const float* __restrict__ qkv,
            bf16* __restrict__ outh, bf16* __restrict__ outl)
{
    extern __shared__ float sm[];
    float* Ks = sm;                       // [NTOK][65]
    float* Vs = Ks + NTOK * KVPAD;        // [NTOK][65]
    float* Qs = Vs + NTOK * KVPAD;        // [8][4][64]

    const int b = blockIdx.x, h = blockIdx.y;
    const int tid = threadIdx.x, lane = tid & 31, warp = tid >> 5;

    for (int idx = tid; idx < NTOK * HD; idx += 256) {
        const int j = idx >> 6, d = idx & 63;
        const size_t g = ((size_t)j * BATCH + b) * (3 * CDIM) + h * HD + d;
        Ks[j * KVPAD + d] = qkv[g + CDIM];
        Vs[j * KVPAD + d] = qkv[g + 2 * CDIM];
    }
    __syncthreads();

    for (int g = 0; g < 7; g++) {         // 7 groups x 4 queries per warp
        // stage 4 queries
        #pragma unroll
        for (int e = 0; e < 4; e++) {
            const int i = warp + 32 * g + 8 * e;
            if (i < NTOK) {
                const size_t qg = ((size_t)i * BATCH + b) * (3 * CDIM) + h * HD;
                Qs[(warp * 4 + e) * HD + lane]      = qkv[qg + lane];
                Qs[(warp * 4 + e) * HD + lane + 32] = qkv[qg + lane + 32];
            }
        }
        __syncwarp();

        float s[4][7];
        #pragma unroll
        for (int e = 0; e < 4; e++)
            #pragma unroll
            for (int t = 0; t < 7; t++) s[e][t] = 0.f;

        #pragma unroll 4
        for (int d = 0; d < HD; d++) {
            const float q0 = Qs[(warp * 4 + 0) * HD + d];
            const float q1 = Qs[(warp * 4 + 1) * HD + d];
            const float q2 = Qs[(warp * 4 + 2) * HD + d];
            const float q3 = Qs[(warp * 4 + 3) * HD + d];
            #pragma unroll
            for (int t = 0; t < 7; t++) {
                const int j = lane + t * 32;
                if (j < NTOK) {
                    const float kv = Ks[j * KVPAD + d];
                    s[0][t] += q0 * kv; s[1][t] += q1 * kv;
                    s[2][t] += q2 * kv; s[3][t] += q3 * kv;
                }
            }
        }

        // softmax per query (probabilities kept in registers)
        #pragma unroll
        for (int e = 0; e < 4; e++) {
            float mx = -1e30f;
            #pragma unroll
            for (int t = 0; t < 7; t++) {
                const int j = lane + t * 32;
                s[e][t] = (j < NTOK) ? s[e][t] * 0.125f : -1e30f;
                mx = fmaxf(mx, s[e][t]);
            }
            #pragma unroll
            for (int o = 16; o; o >>= 1)
                mx = fmaxf(mx, __shfl_xor_sync(0xffffffffu, mx, o));
            float sum = 0.f;
            #pragma unroll
            for (int t = 0; t < 7; t++) {
                const int j = lane + t * 32;
                const float ev = (j < NTOK) ? __expf(s[e][t] - mx) : 0.f;
                s[e][t] = ev; sum += ev;
            }
            #pragma unroll
            for (int o = 16; o; o >>= 1)
                sum += __shfl_xor_sync(0xffffffffu, sum, o);
            const float inv = 1.f / sum;
            #pragma unroll
            for (int t = 0; t < 7; t++) s[e][t] *= inv;
        }

        // o = P @ V, P broadcast via shuffle from score registers
        float a0[4] = {}, a1[4] = {};
        #pragma unroll
        for (int t = 0; t < 7; t++) {
            const int jmax = (t == 6) ? (NTOK - 6 * 32) : 32;   // 5 on last
            for (int jj = 0; jj < jmax; jj++) {
                const int j = t * 32 + jj;
                const float v0 = Vs[j * KVPAD + lane];
                const float v1 = Vs[j * KVPAD + lane + 32];
                #pragma unroll
                for (int e = 0; e < 4; e++) {
                    const float p = __shfl_sync(0xffffffffu, s[e][t], jj);
                    a0[e] += p * v0; a1[e] += p * v1;
                }
            }
        }

        #pragma unroll
        for (int e = 0; e < 4; e++) {
            const int i = warp + 32 * g + 8 * e;
            if (i < NTOK) {
                const size_t og = ((size_t)i * BATCH + b) * CDIM + h * HD;
                bf16 hh, ll;
                split_bf16(a0[e], hh, ll);
                outh[og + lane] = hh;      outl[og + lane] = ll;
                split_bf16(a1[e], hh, ll);
                outh[og + lane + 32] = hh; outl[og + lane + 32] = ll;
            }
        }
        __syncwarp();
    }
}

// ---------------- CLS scores in fp64 straight from ln1 + weights ------------
__global__ void __launch_bounds__(256)
cls_score_kernel(const float* __restrict__ ln1, const float* __restrict__ inw,
                 const float* __restrict__ inb, float* __restrict__ cls)
{
    const int b = blockIdx.x, tid = threadIdx.x;
    const int lane = tid & 31, w = tid >> 5;
    __shared__ float  ln0[CDIM];
    __shared__ double q0[HD];
    __shared__ double wv[CDIM];
    __shared__ double sj[NTOK];
    __shared__ double redd[8];
    __shared__ double beta_s;

    for (int c = tid; c < CDIM; c += 256)
        ln0[c] = ln1[(size_t)b * CDIM + c];
    __syncthreads();

    double acc = 0.0;
    for (int h = 0; h < NH; h++) {
        {
            const int d = tid >> 2, part = tid & 3;
            const float* wr = inw + (size_t)(h * HD + d) * CDIM;
            double s = 0.0;
            const int c0 = part * 192;
            for (int c = c0; c < c0 + 192; c++)
                s += (double)ln0[c] * (double)wr[c];
            s += __shfl_xor_sync(0xffffffffu, s, 1);
            s += __shfl_xor_sync(0xffffffffu, s, 2);
            if (part == 0) q0[d] = s + (double)inb[h * HD + d];
        }
        __syncthreads();
        for (int c = tid; c < CDIM; c += 256) {
            double s = 0.0;
            #pragma unroll 8
            for (int d = 0; d < HD; d++)
                s += q0[d] * (double)inw[(size_t)(CDIM + h * HD + d) * CDIM + c];
            wv[c] = s;
        }
        if (tid == 0) {
            double bsum = 0.0;
            for (int d = 0; d < HD; d++)
                bsum += q0[d] * (double)inb[CDIM + h * HD + d];
            beta_s = bsum;
        }
        __syncthreads();
        for (int j = w; j < NTOK; j += 8) {
            const float* xr = ln1 + ((size_t)j * BATCH + b) * CDIM;
            double s = 0.0;
            for (int c = lane; c < CDIM; c += 32)
                s += (double)xr[c] * wv[c];
            #pragma unroll
            for (int o = 16; o; o >>= 1) s += __shfl_xor_sync(0xffffffffu, s, o);
            if (lane == 0) sj[j] = (s + beta_s) * 0.125;
        }
        __syncthreads();
        double v = (tid < NTOK) ? sj[tid] : -1e300;
        #pragma unroll
        for (int o = 16; o; o >>= 1) v = fmax(v, __shfl_xor_sync(0xffffffffu, v, o));
        if (lane == 0) redd[w] = v;
        __syncthreads();
        double mx = redd[0];
        #pragma unroll
        for (int i = 1; i < 8; i++) mx = fmax(mx, redd[i]);
        const double e = (tid < NTOK) ? exp(sj[tid] - mx) : 0.0;
        double sv = e;
        #pragma unroll
        for (int o = 16; o; o >>= 1) sv += __shfl_xor_sync(0xffffffffu, sv, o);
        __syncthreads();
        if (lane == 0) redd[w] = sv;
        __syncthreads();
        double S = 0.0;
        #pragma unroll
        for (int i = 0; i < 8; i++) S += redd[i];
        if (tid >= 1 && tid < NTOK) acc += e / S;
        __syncthreads();
    }
    if (tid >= 1 && tid < NTOK)
        cls[(size_t)b * NP + (tid - 1)] = (float)(acc * (1.0 / NH));
}

// ---------------- exact stable top-k (value desc, index asc ties) -----------
__global__ void topk_kernel(const float* __restrict__ cls,
                            int* __restrict__ idx, int* __restrict__ comp)
{
    __shared__ float v[NP];
    const int b = blockIdx.x, t = threadIdx.x;
    if (t < NP) v[t] = cls[b * NP + t];
    __syncthreads();
    if (t < NP) {
        const float mv = v[t];
        int r = 0;
        for (int j = 0; j < NP; j++) {
            const float vj = v[j];
            r += (vj > mv) || (vj == mv && j < t);
        }
        if (r < LKEEP) idx[b * LKEEP + r] = t;
        else           comp[b * LKEEP + (r - LKEEP)] = t;
    }
}

// ---------------- build x_new: [cls, topk tokens (desc), fused token] -------
__global__ void gather_kernel(const float* __restrict__ xres,
                              const int* __restrict__ idx,
                              const int* __restrict__ comp,
                              const float* __restrict__ cls,
                              float* __restrict__ xnew)
{
    const int nn = blockIdx.x;
    const int b  = blockIdx.y;
    const int t  = threadIdx.x;
    float* dst = xnew + ((size_t)nn * BATCH + b) * CDIM;

    if (nn == 0) {
        const float* src = xres + (size_t)b * CDIM;
        dst[t] = src[t]; dst[t + 256] = src[t + 256]; dst[t + 512] = src[t + 512];
    } else if (nn <= LKEEP) {
        const int tok = 1 + idx[b * LKEEP + (nn - 1)];
        const float* src = xres + ((size_t)tok * BATCH + b) * CDIM;
        dst[t] = src[t]; dst[t + 256] = src[t + 256]; dst[t + 512] = src[t + 512];
    } else {
        float a0 = 0.f, a1 = 0.f, a2 = 0.f;
        for (int q = 0; q < LKEEP; q++) {
            const int j = comp[b * LKEEP + q];
            const float w = cls[b * NP + j];
            const float* src = xres + ((size_t)(1 + j) * BATCH + b) * CDIM;
            a0 += src[t] * w; a1 += src[t + 256] * w; a2 += src[t + 512] * w;
        }
        dst[t] = a0; dst[t + 256] = a1; dst[t + 512] = a2;
    }
}

// ---------------- launch ----------------------------------------------------
extern "C" void kernel_launch(void* const* d_in, const int* in_sizes, int n_in,
                              void* d_out, int out_size)
{
    const float* x     = (const float*)d_in[0];
    const float* ln1_g = (const float*)d_in[1];
    const float* ln1_b = (const float*)d_in[2];
    const float* in_w  = (const float*)d_in[3];
    const float* in_b  = (const float*)d_in[4];
    const float* ow    = (const float*)d_in[5];
    const float* ob    = (const float*)d_in[6];
    const float* ln2_g = (const float*)d_in[7];
    const float* ln2_b = (const float*)d_in[8];
    const float* fc_w  = (const float*)d_in[9];
    const float* fc_b  = (const float*)d_in[10];
    const float* pj_w  = (const float*)d_in[11];
    const float* pj_b  = (const float*)d_in[12];
    float* out = (float*)d_out;

    float *ln1, *qkv, *xres, *cls, *xnew;
    int *idxp, *compp;
    bf16 *ln1h, *ln1l, *atth, *attl, *ln2h, *ln2l, *fch, *fcl, *wh, *wl;
    cudaGetSymbolAddress((void**)&ln1,   g_ln1);
    cudaGetSymbolAddress((void**)&qkv,   g_qkv);
    cudaGetSymbolAddress((void**)&xres,  g_xres);
    cudaGetSymbolAddress((void**)&cls,   g_cls);
    cudaGetSymbolAddress((void**)&idxp,  g_idx);
    cudaGetSymbolAddress((void**)&compp, g_comp);
    cudaGetSymbolAddress((void**)&xnew,  g_xnew);
    cudaGetSymbolAddress((void**)&ln1h,  g_ln1h);
    cudaGetSymbolAddress((void**)&ln1l,  g_ln1l);
    cudaGetSymbolAddress((void**)&atth,  g_atth);
    cudaGetSymbolAddress((void**)&attl,  g_attl);
    cudaGetSymbolAddress((void**)&ln2h,  g_ln2h);
    cudaGetSymbolAddress((void**)&ln2l,  g_ln2l);
    cudaGetSymbolAddress((void**)&fch,   g_fch);
    cudaGetSymbolAddress((void**)&fcl,   g_fcl);
    cudaGetSymbolAddress((void**)&wh,    g_wh);
    cudaGetSymbolAddress((void**)&wl,    g_wl);

    cudaFuncSetAttribute(attn_kernel, cudaFuncAttributeMaxDynamicSharedMemorySize,
                         ATT_SMEM);
    cudaFuncSetAttribute(bf16_gemm_kernel, cudaFuncAttributeMaxDynamicSharedMemorySize,
                         GSM);

    // 0) split weights into bf16 hi/lo
    convert_kernel<<<(3 * CDIM * CDIM / 4 + 255) / 256, 256>>>(
        in_w, wh + O_INW, wl + O_INW, 3 * CDIM * CDIM / 4);
    convert_kernel<<<(CDIM * CDIM / 4 + 255) / 256, 256>>>(
        ow, wh + O_OW, wl + O_OW, CDIM * CDIM / 4);
    convert_kernel<<<(4 * CDIM * CDIM / 4 + 255) / 256, 256>>>(
        fc_w, wh + O_FCW, wl + O_FCW, 4 * CDIM * CDIM / 4);
    convert_kernel<<<(4 * CDIM * CDIM / 4 + 255) / 256, 256>>>(
        pj_w, wh + O_PJW, wl + O_PJW, 4 * CDIM * CDIM / 4);

    // 1) ln1 (fp32 for cls path + hi/lo for GEMM)
    ln_kernel<<<M1, 256>>>(x, ln1_g, ln1_b, ln1, ln1h, ln1l);
    // 2) qkv = ln1 @ in_proj_w^T + b
    bf16_gemm_kernel<<<dim3(3 * CDIM / 128, M1 / 128), 256, GSM>>>(
        ln1h, ln1l, wh + O_INW, wl + O_INW, in_b, nullptr,
        qkv, nullptr, nullptr, M1, 3 * CDIM, CDIM, 0);
    // 3) attention -> att hi/lo
    attn_kernel<<<dim3(BATCH, NH), 256, ATT_SMEM>>>(qkv, atth, attl);
    // 4) CLS scores in fp64 (exact, GEMM-independent ranking)
    cls_score_kernel<<<BATCH, 256>>>(ln1, in_w, in_b, cls);
    // 5) out_proj + residual x -> xres
    bf16_gemm_kernel<<<dim3(CDIM / 128, M1 / 128), 256, GSM>>>(
        atth, attl, wh + O_OW, wl + O_OW, ob, x,
        xres, nullptr, nullptr, M1, CDIM, CDIM, 0);
    // 6) top-k + complement
    topk_kernel<<<BATCH, 256>>>(cls, idxp, compp);
    // 7) build x_new
    gather_kernel<<<dim3(NNEW, BATCH), 256>>>(xres, idxp, compp, cls, xnew);
    // 8) ln2 -> hi/lo
    ln_kernel<<<M2, 256>>>(xnew, ln2_g, ln2_b, nullptr, ln2h, ln2l);
    // 9) fc + quickgelu -> hi/lo
    bf16_gemm_kernel<<<dim3(4 * CDIM / 128, M2 / 128), 256, GSM>>>(
        ln2h, ln2l, wh + O_FCW, wl + O_FCW, fc_b, nullptr,
        nullptr, fch, fcl, M2, 4 * CDIM, CDIM, 1);
    // 10) proj + residual x_new -> out
    bf16_gemm_kernel<<<dim3(CDIM / 128, M2 / 128), 256, GSM>>>(
        fch, fcl, wh + O_PJW, wl + O_PJW, pj_b, xnew,
        out, nullptr, nullptr, M2, CDIM, 4 * CDIM, 0);
}

// round 7
// speedup vs baseline: 1.6480x; 1.1426x over previous
#include <cuda_runtime.h>
#include <cuda_fp16.h>
#include <math.h>
#include <stdint.h>

#define NTOK  197
#define BATCH 256
#define CDIM  768
#define NH    12
#define HD    64
#define LKEEP 98
#define NP    (NTOK - 1)     // 196
#define NNEW  (LKEEP + 2)    // 100
#define M1    (NTOK * BATCH) // 50432
#define M2    (NNEW * BATCH) // 25600

typedef __half f16;

// ---------------- scratch (device globals; no cudaMalloc allowed) ----------
__device__ float g_ln1 [(size_t)M1 * CDIM];          // fp32 (cls path)
__device__ float g_qkv [(size_t)M1 * 3 * CDIM];
__device__ float g_xres[(size_t)M1 * CDIM];
__device__ float g_cls [(size_t)BATCH * NP];
__device__ int   g_idx [BATCH * LKEEP];
__device__ int   g_comp[BATCH * LKEEP];
__device__ float g_xnew[(size_t)M2 * CDIM];

__device__ f16 g_ln1h[(size_t)M1 * CDIM];
__device__ f16 g_ln1l[(size_t)M1 * CDIM];
__device__ f16 g_atth[(size_t)M1 * CDIM];
__device__ f16 g_attl[(size_t)M1 * CDIM];
__device__ f16 g_ln2h[(size_t)M2 * CDIM];
__device__ f16 g_ln2l[(size_t)M2 * CDIM];
__device__ f16 g_fch [(size_t)M2 * 4 * CDIM];
__device__ f16 g_fcl [(size_t)M2 * 4 * CDIM];
// weights concatenated: in_w | out_w | fc_w | pj_w  (single fp16)
#define O_INW 0
#define O_OW  (3 * CDIM * CDIM)
#define O_FCW (O_OW + CDIM * CDIM)
#define O_PJW (O_FCW + 4 * CDIM * CDIM)
#define W_TOT (O_PJW + 4 * CDIM * CDIM)
__device__ f16 g_wf[W_TOT];

// ---------------- helpers ----------------------------------------------------
__device__ __forceinline__ uint32_t smem_u32(const void* p) {
    uint32_t a;
    asm("{ .reg .u64 t; cvta.to.shared.u64 t, %1; cvt.u32.u64 %0, t; }"
        : "=r"(a) : "l"(p));
    return a;
}
__device__ __forceinline__ void ldsm4(uint32_t r[4], uint32_t addr) {
    asm volatile("ldmatrix.sync.aligned.m8n8.x4.shared.b16 {%0,%1,%2,%3}, [%4];"
        : "=r"(r[0]), "=r"(r[1]), "=r"(r[2]), "=r"(r[3]) : "r"(addr));
}
__device__ __forceinline__ void ldsm2(uint32_t r[2], uint32_t addr) {
    asm volatile("ldmatrix.sync.aligned.m8n8.x2.shared.b16 {%0,%1}, [%2];"
        : "=r"(r[0]), "=r"(r[1]) : "r"(addr));
}
__device__ __forceinline__ void mma_f16(float c[4], const uint32_t a[4],
                                        const uint32_t b[2]) {
    asm volatile("mma.sync.aligned.m16n8k16.row.col.f32.f16.f16.f32 "
        "{%0,%1,%2,%3}, {%4,%5,%6,%7}, {%8,%9}, {%0,%1,%2,%3};"
        : "+f"(c[0]), "+f"(c[1]), "+f"(c[2]), "+f"(c[3])
        : "r"(a[0]), "r"(a[1]), "r"(a[2]), "r"(a[3]), "r"(b[0]), "r"(b[1]));
}
__device__ __forceinline__ void split_f16(float x, f16& h, f16& l) {
    h = __float2half_rn(x);
    l = __float2half_rn(x - __half2float(h));
}
__device__ __forceinline__ void cp16(uint32_t dst, const void* src) {
    asm volatile("cp.async.cg.shared.global [%0], [%1], 16;"
                 :: "r"(dst), "l"(src));
}

// ---------------- fp32 -> fp16 weight converter ------------------------------
__global__ void convert_w_kernel(const float* __restrict__ s,
                                 f16* __restrict__ d, int n4)
{
    const int i = blockIdx.x * 256 + threadIdx.x;
    if (i >= n4) return;
    float4 v = ((const float4*)s)[i];
    ((__half2*)d)[2 * i]     = __floats2half2_rn(v.x, v.y);
    ((__half2*)d)[2 * i + 1] = __floats2half2_rn(v.z, v.w);
}

// ---------------- layernorm: one block per row of 768 ----------------------
__global__ void ln_kernel(const float* __restrict__ x,
                          const float* __restrict__ gam,
                          const float* __restrict__ bet,
                          float* __restrict__ y,
                          f16* __restrict__ yh, f16* __restrict__ yl)
{
    const int row = blockIdx.x;
    const int t   = threadIdx.x;
    const float* xr = x + (size_t)row * CDIM;

    float v0 = xr[t], v1 = xr[t + 256], v2 = xr[t + 512];
    float s  = v0 + v1 + v2;
    float ss = v0 * v0 + v1 * v1 + v2 * v2;

    __shared__ float red[16];
    #pragma unroll
    for (int o = 16; o; o >>= 1) {
        s  += __shfl_xor_sync(0xffffffffu, s,  o);
        ss += __shfl_xor_sync(0xffffffffu, ss, o);
    }
    const int warp = t >> 5, lane = t & 31;
    if (lane == 0) { red[warp] = s; red[warp + 8] = ss; }
    __syncthreads();
    float S = 0.f, SS = 0.f;
    #pragma unroll
    for (int i = 0; i < 8; i++) { S += red[i]; SS += red[i + 8]; }

    const float mu  = S * (1.f / CDIM);
    const float var = SS * (1.f / CDIM) - mu * mu;
    const float inv = rsqrtf(var + 1e-5f);

    const size_t base = (size_t)row * CDIM;
    #pragma unroll
    for (int e = 0; e < 3; e++) {
        const int c = t + e * 256;
        const float v = (e == 0 ? v0 : (e == 1 ? v1 : v2));
        const float o = (v - mu) * inv * gam[c] + bet[c];
        if (y) y[base + c] = o;
        f16 h, l; split_f16(o, h, l);
        yh[base + c] = h; yl[base + c] = l;
    }
}

// ---------------- fp16x2 mma.sync GEMM, 4-stage cp.async pipeline -----------
// C[M,N] = A[M,K] @ W[N,K]^T + bias (+act) (+res).
// A pre-split fp16 hi/lo (error ~2^-23); W single fp16 (error ~2.8e-4).
// 128x128 CTA tile, 8 warps (2m x 4n), warp tile 64x32, K-chunk 32.
#define ROWB   80                    // smem bytes per row: 32 f16 + 8 pad
#define TBYTES (128 * ROWB)          // 10240 per operand tensor
#define STG    (3 * TBYTES)          // 30720 per stage (A_hi, A_lo, W)
#define NSTAGE 4
#define GSM    (NSTAGE * STG)        // 122880

__global__ void __launch_bounds__(256)
f16_gemm_kernel(const f16* __restrict__ Ah, const f16* __restrict__ Al,
                const f16* __restrict__ Wf,
                const float* __restrict__ bias, const float* __restrict__ res,
                float* __restrict__ Cf, f16* __restrict__ Ch,
                f16* __restrict__ Cl, int M, int Nn, int K, int act)
{
    extern __shared__ char dsm[];
    const uint32_t sb = smem_u32(dsm);

    const int tid = threadIdx.x, lane = tid & 31, wid = tid >> 5;
    const int wm = wid >> 2, wn = wid & 3;
    const int m0 = blockIdx.y * 128, n0 = blockIdx.x * 128;

    float acc[4][4][4] = {};

    auto issue = [&](int s, int t) {
        const int k0 = t << 5;
        #pragma unroll
        for (int r = 0; r < 6; r++) {
            const int id = tid + (r << 8);           // 0..1535
            const int tensor = id >> 9;              // 0..2
            const int w = id & 511;
            const int row = w >> 2, c4 = w & 3;      // 16B unit within 64B row
            const f16* src;
            if      (tensor == 0) src = Ah + (size_t)(m0 + row) * K + k0 + c4 * 8;
            else if (tensor == 1) src = Al + (size_t)(m0 + row) * K + k0 + c4 * 8;
            else                  src = Wf + (size_t)(n0 + row) * K + k0 + c4 * 8;
            const uint32_t dst = sb + (uint32_t)(s * STG + tensor * TBYTES
                                                 + row * ROWB + c4 * 16);
            cp16(dst, src);
        }
        asm volatile("cp.async.commit_group;" ::: "memory");
    };

    const int nch = K >> 5;                          // >= 24 always here
    issue(0, 0);
    issue(1, 1);
    issue(2, 2);

    for (int t = 0; t < nch; t++) {
        asm volatile("cp.async.wait_group 2;" ::: "memory");
        __syncthreads();
        if (t + 3 < nch) issue((t + 3) % NSTAGE, t + 3);
        else asm volatile("cp.async.commit_group;" ::: "memory");

        const uint32_t sA = sb + (uint32_t)((t % NSTAGE) * STG);
        #pragma unroll
        for (int ks = 0; ks < 2; ks++) {
            uint32_t ah[4][4], al[4][4];
            #pragma unroll
            for (int mf = 0; mf < 4; mf++) {
                const uint32_t ra = sA +
                    (uint32_t)((wm * 64 + mf * 16 + (lane & 15)) * ROWB
                               + ks * 32 + ((lane >> 4) << 4));
                ldsm4(ah[mf], ra);
                ldsm4(al[mf], ra + TBYTES);
            }
            #pragma unroll
            for (int nf = 0; nf < 4; nf++) {
                const uint32_t rb = sA + 2 * TBYTES +
                    (uint32_t)((wn * 32 + nf * 8 + (lane & 7)) * ROWB
                               + ks * 32 + (((lane >> 3) & 1) << 4));
                uint32_t bh[2];
                ldsm2(bh, rb);
                #pragma unroll
                for (int mf = 0; mf < 4; mf++) {
                    mma_f16(acc[mf][nf], ah[mf], bh);
                    mma_f16(acc[mf][nf], al[mf], bh);
                }
            }
        }
    }

    // epilogue
    #pragma unroll
    for (int mf = 0; mf < 4; mf++) {
        #pragma unroll
        for (int nf = 0; nf < 4; nf++) {
            const int rr = m0 + wm * 64 + mf * 16 + (lane >> 2);
            const int cc = n0 + wn * 32 + nf * 8 + ((lane & 3) << 1);
            const float b0 = bias[cc], b1 = bias[cc + 1];
            float v0 = acc[mf][nf][0] + b0;
            float v1 = acc[mf][nf][1] + b1;
            float v2 = acc[mf][nf][2] + b0;
            float v3 = acc[mf][nf][3] + b1;
            if (act) {
                v0 = v0 / (1.f + __expf(-1.702f * v0));
                v1 = v1 / (1.f + __expf(-1.702f * v1));
                v2 = v2 / (1.f + __expf(-1.702f * v2));
                v3 = v3 / (1.f + __expf(-1.702f * v3));
            }
            const size_t o0 = (size_t)rr * Nn + cc;
            const size_t o1 = (size_t)(rr + 8) * Nn + cc;
            if (Cf) {
                if (res) {
                    float2 r0 = *(const float2*)(res + o0);
                    float2 r1 = *(const float2*)(res + o1);
                    v0 += r0.x; v1 += r0.y; v2 += r1.x; v3 += r1.y;
                }
                float2 s0; s0.x = v0; s0.y = v1;
                float2 s1; s1.x = v2; s1.y = v3;
                *(float2*)(Cf + o0) = s0;
                *(float2*)(Cf + o1) = s1;
            } else {
                f16 h, l; __half2 hh, ll;
                split_f16(v0, h, l); hh.x = h; ll.x = l;
                split_f16(v1, h, l); hh.y = h; ll.y = l;
                *(__half2*)(Ch + o0) = hh; *(__half2*)(Cl + o0) = ll;
                split_f16(v2, h, l); hh.x = h; ll.x = l;
                split_f16(v3, h, l); hh.y = h; ll.y = l;
                *(__half2*)(Ch + o1) = hh; *(__half2*)(Cl + o1) = ll;
            }
        }
    }
}

// ---------------- attention: 4 queries per warp pass, P via shuffle ---------
#define KVPAD 65
#define ATT_SMEM ((2 * NTOK * KVPAD + 8 * 4 * HD) * (int)sizeof(float))

__global__ void __launch_bounds__(256)
attn_kernel(const float* __restrict__ qkv,
            f16* __restrict__ outh, f16* __restrict__ outl)
{
    extern __shared__ float sm[];
    float* Ks = sm;                       // [NTOK][65]
    float* Vs = Ks + NTOK * KVPAD;        // [NTOK][65]
    float* Qs = Vs + NTOK * KVPAD;        // [8][4][64]

    const int b = blockIdx.x, h = blockIdx.y;
    const int tid = threadIdx.x, lane = tid & 31, warp = tid >> 5;

    for (int idx = tid; idx < NTOK * HD; idx += 256) {
        const int j = idx >> 6, d = idx & 63;
        const size_t g = ((size_t)j * BATCH + b) * (3 * CDIM) + h * HD + d;
        Ks[j * KVPAD + d] = qkv[g + CDIM];
        Vs[j * KVPAD + d] = qkv[g + 2 * CDIM];
    }
    __syncthreads();

    for (int g = 0; g < 7; g++) {
        #pragma unroll
        for (int e = 0; e < 4; e++) {
            const int i = warp + 32 * g + 8 * e;
            if (i < NTOK) {
                const size_t qg = ((size_t)i * BATCH + b) * (3 * CDIM) + h * HD;
                Qs[(warp * 4 + e) * HD + lane]      = qkv[qg + lane];
                Qs[(warp * 4 + e) * HD + lane + 32] = qkv[qg + lane + 32];
            }
        }
        __syncwarp();

        float s[4][7];
        #pragma unroll
        for (int e = 0; e < 4; e++)
            #pragma unroll
            for (int t = 0; t < 7; t++) s[e][t] = 0.f;

        #pragma unroll 4
        for (int d = 0; d < HD; d++) {
            const float q0 = Qs[(warp * 4 + 0) * HD + d];
            const float q1 = Qs[(warp * 4 + 1) * HD + d];
            const float q2 = Qs[(warp * 4 + 2) * HD + d];
            const float q3 = Qs[(warp * 4 + 3) * HD + d];
            #pragma unroll
            for (int t = 0; t < 7; t++) {
                const int j = lane + t * 32;
                if (j < NTOK) {
                    const float kv = Ks[j * KVPAD + d];
                    s[0][t] += q0 * kv; s[1][t] += q1 * kv;
                    s[2][t] += q2 * kv; s[3][t] += q3 * kv;
                }
            }
        }

        #pragma unroll
        for (int e = 0; e < 4; e++) {
            float mx = -1e30f;
            #pragma unroll
            for (int t = 0; t < 7; t++) {
                const int j = lane + t * 32;
                s[e][t] = (j < NTOK) ? s[e][t] * 0.125f : -1e30f;
                mx = fmaxf(mx, s[e][t]);
            }
            #pragma unroll
            for (int o = 16; o; o >>= 1)
                mx = fmaxf(mx, __shfl_xor_sync(0xffffffffu, mx, o));
            float sum = 0.f;
            #pragma unroll
            for (int t = 0; t < 7; t++) {
                const int j = lane + t * 32;
                const float ev = (j < NTOK) ? __expf(s[e][t] - mx) : 0.f;
                s[e][t] = ev; sum += ev;
            }
            #pragma unroll
            for (int o = 16; o; o >>= 1)
                sum += __shfl_xor_sync(0xffffffffu, sum, o);
            const float inv = 1.f / sum;
            #pragma unroll
            for (int t = 0; t < 7; t++) s[e][t] *= inv;
        }

        float a0[4] = {}, a1[4] = {};
        #pragma unroll
        for (int t = 0; t < 7; t++) {
            const int jmax = (t == 6) ? (NTOK - 6 * 32) : 32;
            for (int jj = 0; jj < jmax; jj++) {
                const int j = t * 32 + jj;
                const float v0 = Vs[j * KVPAD + lane];
                const float v1 = Vs[j * KVPAD + lane + 32];
                #pragma unroll
                for (int e = 0; e < 4; e++) {
                    const float p = __shfl_sync(0xffffffffu, s[e][t], jj);
                    a0[e] += p * v0; a1[e] += p * v1;
                }
            }
        }

        #pragma unroll
        for (int e = 0; e < 4; e++) {
            const int i = warp + 32 * g + 8 * e;
            if (i < NTOK) {
                const size_t og = ((size_t)i * BATCH + b) * CDIM + h * HD;
                f16 hh, ll;
                split_f16(a0[e], hh, ll);
                outh[og + lane] = hh;      outl[og + lane] = ll;
                split_f16(a1[e], hh, ll);
                outh[og + lane + 32] = hh; outl[og + lane + 32] = ll;
            }
        }
        __syncwarp();
    }
}

// ---------------- CLS scores in fp64 straight from ln1 + weights ------------
__global__ void __launch_bounds__(256)
cls_score_kernel(const float* __restrict__ ln1, const float* __restrict__ inw,
                 const float* __restrict__ inb, float* __restrict__ cls)
{
    const int b = blockIdx.x, tid = threadIdx.x;
    const int lane = tid & 31, w = tid >> 5;
    __shared__ float  ln0[CDIM];
    __shared__ double q0[HD];
    __shared__ double wv[CDIM];
    __shared__ double sj[NTOK];
    __shared__ double redd[8];
    __shared__ double beta_s;

    for (int c = tid; c < CDIM; c += 256)
        ln0[c] = ln1[(size_t)b * CDIM + c];
    __syncthreads();

    double acc = 0.0;
    for (int h = 0; h < NH; h++) {
        {
            const int d = tid >> 2, part = tid & 3;
            const float* wr = inw + (size_t)(h * HD + d) * CDIM;
            double s = 0.0;
            const int c0 = part * 192;
            for (int c = c0; c < c0 + 192; c++)
                s += (double)ln0[c] * (double)wr[c];
            s += __shfl_xor_sync(0xffffffffu, s, 1);
            s += __shfl_xor_sync(0xffffffffu, s, 2);
            if (part == 0) q0[d] = s + (double)inb[h * HD + d];
        }
        __syncthreads();
        for (int c = tid; c < CDIM; c += 256) {
            double s = 0.0;
            #pragma unroll 8
            for (int d = 0; d < HD; d++)
                s += q0[d] * (double)inw[(size_t)(CDIM + h * HD + d) * CDIM + c];
            wv[c] = s;
        }
        if (tid == 0) {
            double bsum = 0.0;
            for (int d = 0; d < HD; d++)
                bsum += q0[d] * (double)inb[CDIM + h * HD + d];
            beta_s = bsum;
        }
        __syncthreads();
        for (int j = w; j < NTOK; j += 8) {
            const float* xr = ln1 + ((size_t)j * BATCH + b) * CDIM;
            double s = 0.0;
            for (int c = lane; c < CDIM; c += 32)
                s += (double)xr[c] * wv[c];
            #pragma unroll
            for (int o = 16; o; o >>= 1) s += __shfl_xor_sync(0xffffffffu, s, o);
            if (lane == 0) sj[j] = (s + beta_s) * 0.125;
        }
        __syncthreads();
        double v = (tid < NTOK) ? sj[tid] : -1e300;
        #pragma unroll
        for (int o = 16; o; o >>= 1) v = fmax(v, __shfl_xor_sync(0xffffffffu, v, o));
        if (lane == 0) redd[w] = v;
        __syncthreads();
        double mx = redd[0];
        #pragma unroll
        for (int i = 1; i < 8; i++) mx = fmax(mx, redd[i]);
        const double e = (tid < NTOK) ? exp(sj[tid] - mx) : 0.0;
        double sv = e;
        #pragma unroll
        for (int o = 16; o; o >>= 1) sv += __shfl_xor_sync(0xffffffffu, sv, o);
        __syncthreads();
        if (lane == 0) redd[w] = sv;
        __syncthreads();
        double S = 0.0;
        #pragma unroll
        for (int i = 0; i < 8; i++) S += redd[i];
        if (tid >= 1 && tid < NTOK) acc += e / S;
        __syncthreads();
    }
    if (tid >= 1 && tid < NTOK)
        cls[(size_t)b * NP + (tid - 1)] = (float)(acc * (1.0 / NH));
}

// ---------------- exact stable top-k (value desc, index asc ties) -----------
__global__ void topk_kernel(const float* __restrict__ cls,
                            int* __restrict__ idx, int* __restrict__ comp)
{
    __shared__ float v[NP];
    const int b = blockIdx.x, t = threadIdx.x;
    if (t < NP) v[t] = cls[b * NP + t];
    __syncthreads();
    if (t < NP) {
        const float mv = v[t];
        int r = 0;
        for (int j = 0; j < NP; j++) {
            const float vj = v[j];
            r += (vj > mv) || (vj == mv && j < t);
        }
        if (r < LKEEP) idx[b * LKEEP + r] = t;
        else           comp[b * LKEEP + (r - LKEEP)] = t;
    }
}

// ---------------- build x_new: [cls, topk tokens (desc), fused token] -------
__global__ void gather_kernel(const float* __restrict__ xres,
                              const int* __restrict__ idx,
                              const int* __restrict__ comp,
                              const float* __restrict__ cls,
                              float* __restrict__ xnew)
{
    const int nn = blockIdx.x;
    const int b  = blockIdx.y;
    const int t  = threadIdx.x;
    float* dst = xnew + ((size_t)nn * BATCH + b) * CDIM;

    if (nn == 0) {
        const float* src = xres + (size_t)b * CDIM;
        dst[t] = src[t]; dst[t + 256] = src[t + 256]; dst[t + 512] = src[t + 512];
    } else if (nn <= LKEEP) {
        const int tok = 1 + idx[b * LKEEP + (nn - 1)];
        const float* src = xres + ((size_t)tok * BATCH + b) * CDIM;
        dst[t] = src[t]; dst[t + 256] = src[t + 256]; dst[t + 512] = src[t + 512];
    } else {
        float a0 = 0.f, a1 = 0.f, a2 = 0.f;
        for (int q = 0; q < LKEEP; q++) {
            const int j = comp[b * LKEEP + q];
            const float w = cls[b * NP + j];
            const float* src = xres + ((size_t)(1 + j) * BATCH + b) * CDIM;
            a0 += src[t] * w; a1 += src[t + 256] * w; a2 += src[t + 512] * w;
        }
        dst[t] = a0; dst[t + 256] = a1; dst[t + 512] = a2;
    }
}

// ---------------- launch ----------------------------------------------------
extern "C" void kernel_launch(void* const* d_in, const int* in_sizes, int n_in,
                              void* d_out, int out_size)
{
    const float* x     = (const float*)d_in[0];
    const float* ln1_g = (const float*)d_in[1];
    const float* ln1_b = (const float*)d_in[2];
    const float* in_w  = (const float*)d_in[3];
    const float* in_b  = (const float*)d_in[4];
    const float* ow    = (const float*)d_in[5];
    const float* ob    = (const float*)d_in[6];
    const float* ln2_g = (const float*)d_in[7];
    const float* ln2_b = (const float*)d_in[8];
    const float* fc_w  = (const float*)d_in[9];
    const float* fc_b  = (const float*)d_in[10];
    const float* pj_w  = (const float*)d_in[11];
    const float* pj_b  = (const float*)d_in[12];
    float* out = (float*)d_out;

    float *ln1, *qkv, *xres, *cls, *xnew;
    int *idxp, *compp;
    f16 *ln1h, *ln1l, *atth, *attl, *ln2h, *ln2l, *fch, *fcl, *wf;
    cudaGetSymbolAddress((void**)&ln1,   g_ln1);
    cudaGetSymbolAddress((void**)&qkv,   g_qkv);
    cudaGetSymbolAddress((void**)&xres,  g_xres);
    cudaGetSymbolAddress((void**)&cls,   g_cls);
    cudaGetSymbolAddress((void**)&idxp,  g_idx);
    cudaGetSymbolAddress((void**)&compp, g_comp);
    cudaGetSymbolAddress((void**)&xnew,  g_xnew);
    cudaGetSymbolAddress((void**)&ln1h,  g_ln1h);
    cudaGetSymbolAddress((void**)&ln1l,  g_ln1l);
    cudaGetSymbolAddress((void**)&atth,  g_atth);
    cudaGetSymbolAddress((void**)&attl,  g_attl);
    cudaGetSymbolAddress((void**)&ln2h,  g_ln2h);
    cudaGetSymbolAddress((void**)&ln2l,  g_ln2l);
    cudaGetSymbolAddress((void**)&fch,   g_fch);
    cudaGetSymbolAddress((void**)&fcl,   g_fcl);
    cudaGetSymbolAddress((void**)&wf,    g_wf);

    cudaFuncSetAttribute(attn_kernel, cudaFuncAttributeMaxDynamicSharedMemorySize,
                         ATT_SMEM);
    cudaFuncSetAttribute(f16_gemm_kernel, cudaFuncAttributeMaxDynamicSharedMemorySize,
                         GSM);

    // 0) weights -> fp16
    convert_w_kernel<<<(3 * CDIM * CDIM / 4 + 255) / 256, 256>>>(
        in_w, wf + O_INW, 3 * CDIM * CDIM / 4);
    convert_w_kernel<<<(CDIM * CDIM / 4 + 255) / 256, 256>>>(
        ow, wf + O_OW, CDIM * CDIM / 4);
    convert_w_kernel<<<(4 * CDIM * CDIM / 4 + 255) / 256, 256>>>(
        fc_w, wf + O_FCW, 4 * CDIM * CDIM / 4);
    convert_w_kernel<<<(4 * CDIM * CDIM / 4 + 255) / 256, 256>>>(
        pj_w, wf + O_PJW, 4 * CDIM * CDIM / 4);

    // 1) ln1 (fp32 for cls path + fp16 hi/lo for GEMM)
    ln_kernel<<<M1, 256>>>(x, ln1_g, ln1_b, ln1, ln1h, ln1l);
    // 2) qkv = ln1 @ in_proj_w^T + b
    f16_gemm_kernel<<<dim3(3 * CDIM / 128, M1 / 128), 256, GSM>>>(
        ln1h, ln1l, wf + O_INW, in_b, nullptr,
        qkv, nullptr, nullptr, M1, 3 * CDIM, CDIM, 0);
    // 3) attention -> att hi/lo
    attn_kernel<<<dim3(BATCH, NH), 256, ATT_SMEM>>>(qkv, atth, attl);
    // 4) CLS scores in fp64 (exact, GEMM-independent ranking)
    cls_score_kernel<<<BATCH, 256>>>(ln1, in_w, in_b, cls);
    // 5) out_proj + residual x -> xres
    f16_gemm_kernel<<<dim3(CDIM / 128, M1 / 128), 256, GSM>>>(
        atth, attl, wf + O_OW, ob, x,
        xres, nullptr, nullptr, M1, CDIM, CDIM, 0);
    // 6) top-k + complement
    topk_kernel<<<BATCH, 256>>>(cls, idxp, compp);
    // 7) build x_new
    gather_kernel<<<dim3(NNEW, BATCH), 256>>>(xres, idxp, compp, cls, xnew);
    // 8) ln2 -> hi/lo
    ln_kernel<<<M2, 256>>>(xnew, ln2_g, ln2_b, nullptr, ln2h, ln2l);
    // 9) fc + quickgelu -> hi/lo
    f16_gemm_kernel<<<dim3(4 * CDIM / 128, M2 / 128), 256, GSM>>>(
        ln2h, ln2l, wf + O_FCW, fc_b, nullptr,
        nullptr, fch, fcl, M2, 4 * CDIM, CDIM, 1);
    // 10) proj + residual x_new -> out
    f16_gemm_kernel<<<dim3(CDIM / 128, M2 / 128), 256, GSM>>>(
        fch, fcl, wf + O_PJW, pj_b, xnew,
        out, nullptr, nullptr, M2, CDIM, 4 * CDIM, 0);
}

// round 8
// speedup vs baseline: 1.9150x; 1.1620x over previous
#include <cuda_runtime.h>
#include <cuda_fp16.h>
#include <math.h>
#include <stdint.h>

#define NTOK  197
#define BATCH 256
#define CDIM  768
#define NH    12
#define HD    64
#define LKEEP 98
#define NP    (NTOK - 1)     // 196
#define NNEW  (LKEEP + 2)    // 100
#define M1    (NTOK * BATCH) // 50432
#define M2    (NNEW * BATCH) // 25600

typedef __half f16;

// ---------------- scratch (device globals; no cudaMalloc allowed) ----------
__device__ float g_ln1 [(size_t)M1 * CDIM];          // fp32 (cls path)
__device__ float g_qkv [(size_t)M1 * 3 * CDIM];
__device__ float g_xres[(size_t)M1 * CDIM];
__device__ float g_cls [(size_t)BATCH * NP];
__device__ int   g_idx [BATCH * LKEEP];
__device__ int   g_comp[BATCH * LKEEP];
__device__ float g_xnew[(size_t)M2 * CDIM];

__device__ f16 g_ln1f[(size_t)M1 * CDIM];
__device__ f16 g_attf[(size_t)M1 * CDIM];
__device__ f16 g_ln2f[(size_t)M2 * CDIM];
__device__ f16 g_fcf [(size_t)M2 * 4 * CDIM];
// weights concatenated: in_w | out_w | fc_w | pj_w  (single fp16)
#define O_INW 0
#define O_OW  (3 * CDIM * CDIM)
#define O_FCW (O_OW + CDIM * CDIM)
#define O_PJW (O_FCW + 4 * CDIM * CDIM)
#define W_TOT (O_PJW + 4 * CDIM * CDIM)
__device__ f16 g_wf[W_TOT];

// ---------------- helpers ----------------------------------------------------
__device__ __forceinline__ uint32_t smem_u32(const void* p) {
    uint32_t a;
    asm("{ .reg .u64 t; cvta.to.shared.u64 t, %1; cvt.u32.u64 %0, t; }"
        : "=r"(a) : "l"(p));
    return a;
}
__device__ __forceinline__ void ldsm4(uint32_t r[4], uint32_t addr) {
    asm volatile("ldmatrix.sync.aligned.m8n8.x4.shared.b16 {%0,%1,%2,%3}, [%4];"
        : "=r"(r[0]), "=r"(r[1]), "=r"(r[2]), "=r"(r[3]) : "r"(addr));
}
__device__ __forceinline__ void ldsm2(uint32_t r[2], uint32_t addr) {
    asm volatile("ldmatrix.sync.aligned.m8n8.x2.shared.b16 {%0,%1}, [%2];"
        : "=r"(r[0]), "=r"(r[1]) : "r"(addr));
}
__device__ __forceinline__ void mma_f16(float c[4], const uint32_t a[4],
                                        const uint32_t b[2]) {
    asm volatile("mma.sync.aligned.m16n8k16.row.col.f32.f16.f16.f32 "
        "{%0,%1,%2,%3}, {%4,%5,%6,%7}, {%8,%9}, {%0,%1,%2,%3};"
        : "+f"(c[0]), "+f"(c[1]), "+f"(c[2]), "+f"(c[3])
        : "r"(a[0]), "r"(a[1]), "r"(a[2]), "r"(a[3]), "r"(b[0]), "r"(b[1]));
}
__device__ __forceinline__ void cp16(uint32_t dst, const void* src) {
    asm volatile("cp.async.cg.shared.global [%0], [%1], 16;"
                 :: "r"(dst), "l"(src));
}

// ---------------- fp32 -> fp16 converter -------------------------------------
__global__ void convert_w_kernel(const float* __restrict__ s,
                                 f16* __restrict__ d, int n4)
{
    const int i = blockIdx.x * 256 + threadIdx.x;
    if (i >= n4) return;
    float4 v = ((const float4*)s)[i];
    ((__half2*)d)[2 * i]     = __floats2half2_rn(v.x, v.y);
    ((__half2*)d)[2 * i + 1] = __floats2half2_rn(v.z, v.w);
}

// ---------------- layernorm: one block per row of 768 ----------------------
__global__ void ln_kernel(const float* __restrict__ x,
                          const float* __restrict__ gam,
                          const float* __restrict__ bet,
                          float* __restrict__ y,
                          f16* __restrict__ yf)
{
    const int row = blockIdx.x;
    const int t   = threadIdx.x;
    const float* xr = x + (size_t)row * CDIM;

    float v0 = xr[t], v1 = xr[t + 256], v2 = xr[t + 512];
    float s  = v0 + v1 + v2;
    float ss = v0 * v0 + v1 * v1 + v2 * v2;

    __shared__ float red[16];
    #pragma unroll
    for (int o = 16; o; o >>= 1) {
        s  += __shfl_xor_sync(0xffffffffu, s,  o);
        ss += __shfl_xor_sync(0xffffffffu, ss, o);
    }
    const int warp = t >> 5, lane = t & 31;
    if (lane == 0) { red[warp] = s; red[warp + 8] = ss; }
    __syncthreads();
    float S = 0.f, SS = 0.f;
    #pragma unroll
    for (int i = 0; i < 8; i++) { S += red[i]; SS += red[i + 8]; }

    const float mu  = S * (1.f / CDIM);
    const float var = SS * (1.f / CDIM) - mu * mu;
    const float inv = rsqrtf(var + 1e-5f);

    const size_t base = (size_t)row * CDIM;
    #pragma unroll
    for (int e = 0; e < 3; e++) {
        const int c = t + e * 256;
        const float v = (e == 0 ? v0 : (e == 1 ? v1 : v2));
        const float o = (v - mu) * inv * gam[c] + bet[c];
        if (y) y[base + c] = o;
        yf[base + c] = __float2half_rn(o);
    }
}

// ---------------- fp16 mma.sync GEMM, 4-stage cp.async pipeline -------------
// C[M,N] = A[M,K] @ W[N,K]^T + bias (+act) (+res). A, W single fp16.
// 128x128 CTA tile, 8 warps (2m x 4n), warp tile 64x32, K-chunk 32.
#define ROWB   80                    // smem bytes per row: 32 f16 + 8 pad
#define TBYTES (128 * ROWB)          // 10240 per operand tensor
#define STG    (2 * TBYTES)          // 20480 per stage (A, W)
#define NSTAGE 4
#define GSM    (NSTAGE * STG)        // 81920

__global__ void __launch_bounds__(256)
f16_gemm_kernel(const f16* __restrict__ Af, const f16* __restrict__ Wf,
                const float* __restrict__ bias, const float* __restrict__ res,
                float* __restrict__ Cf, f16* __restrict__ Ch,
                int M, int Nn, int K, int act)
{
    extern __shared__ char dsm[];
    const uint32_t sb = smem_u32(dsm);

    const int tid = threadIdx.x, lane = tid & 31, wid = tid >> 5;
    const int wm = wid >> 2, wn = wid & 3;
    const int m0 = blockIdx.y * 128, n0 = blockIdx.x * 128;

    float acc[4][4][4] = {};

    auto issue = [&](int s, int t) {
        const int k0 = t << 5;
        #pragma unroll
        for (int r = 0; r < 4; r++) {
            const int id = tid + (r << 8);           // 0..1023
            const int tensor = id >> 9;              // 0..1
            const int w = id & 511;
            const int row = w >> 2, c4 = w & 3;      // 16B unit within 64B row
            const f16* src = (tensor == 0)
                ? Af + (size_t)(m0 + row) * K + k0 + c4 * 8
                : Wf + (size_t)(n0 + row) * K + k0 + c4 * 8;
            const uint32_t dst = sb + (uint32_t)(s * STG + tensor * TBYTES
                                                 + row * ROWB + c4 * 16);
            cp16(dst, src);
        }
        asm volatile("cp.async.commit_group;" ::: "memory");
    };

    const int nch = K >> 5;                          // >= 24 here
    issue(0, 0);
    issue(1, 1);
    issue(2, 2);

    for (int t = 0; t < nch; t++) {
        asm volatile("cp.async.wait_group 2;" ::: "memory");
        __syncthreads();
        if (t + 3 < nch) issue((t + 3) % NSTAGE, t + 3);
        else asm volatile("cp.async.commit_group;" ::: "memory");

        const uint32_t sA = sb + (uint32_t)((t % NSTAGE) * STG);
        #pragma unroll
        for (int ks = 0; ks < 2; ks++) {
            uint32_t ah[4][4];
            #pragma unroll
            for (int mf = 0; mf < 4; mf++) {
                const uint32_t ra = sA +
                    (uint32_t)((wm * 64 + mf * 16 + (lane & 15)) * ROWB
                               + ks * 32 + ((lane >> 4) << 4));
                ldsm4(ah[mf], ra);
            }
            #pragma unroll
            for (int nf = 0; nf < 4; nf++) {
                const uint32_t rb = sA + TBYTES +
                    (uint32_t)((wn * 32 + nf * 8 + (lane & 7)) * ROWB
                               + ks * 32 + (((lane >> 3) & 1) << 4));
                uint32_t bh[2];
                ldsm2(bh, rb);
                #pragma unroll
                for (int mf = 0; mf < 4; mf++)
                    mma_f16(acc[mf][nf], ah[mf], bh);
            }
        }
    }

    // epilogue
    #pragma unroll
    for (int mf = 0; mf < 4; mf++) {
        #pragma unroll
        for (int nf = 0; nf < 4; nf++) {
            const int rr = m0 + wm * 64 + mf * 16 + (lane >> 2);
            const int cc = n0 + wn * 32 + nf * 8 + ((lane & 3) << 1);
            const float b0 = bias[cc], b1 = bias[cc + 1];
            float v0 = acc[mf][nf][0] + b0;
            float v1 = acc[mf][nf][1] + b1;
            float v2 = acc[mf][nf][2] + b0;
            float v3 = acc[mf][nf][3] + b1;
            if (act) {
                v0 = v0 / (1.f + __expf(-1.702f * v0));
                v1 = v1 / (1.f + __expf(-1.702f * v1));
                v2 = v2 / (1.f + __expf(-1.702f * v2));
                v3 = v3 / (1.f + __expf(-1.702f * v3));
            }
            const size_t o0 = (size_t)rr * Nn + cc;
            const size_t o1 = (size_t)(rr + 8) * Nn + cc;
            if (Cf) {
                if (res) {
                    float2 r0 = *(const float2*)(res + o0);
                    float2 r1 = *(const float2*)(res + o1);
                    v0 += r0.x; v1 += r0.y; v2 += r1.x; v3 += r1.y;
                }
                float2 s0; s0.x = v0; s0.y = v1;
                float2 s1; s1.x = v2; s1.y = v3;
                *(float2*)(Cf + o0) = s0;
                *(float2*)(Cf + o1) = s1;
            } else {
                *(__half2*)(Ch + o0) = __floats2half2_rn(v0, v1);
                *(__half2*)(Ch + o1) = __floats2half2_rn(v2, v3);
            }
        }
    }
}

// ---------------- attention: 4 queries per warp pass, P via shuffle ---------
#define KVPAD 65
#define ATT_SMEM ((2 * NTOK * KVPAD + 8 * 4 * HD) * (int)sizeof(float))

__global__ void __launch_bounds__(256)
attn_kernel(const float* __restrict__ qkv, f16* __restrict__ outf)
{
    extern __shared__ float sm[];
    float* Ks = sm;                       // [NTOK][65]
    float* Vs = Ks + NTOK * KVPAD;        // [NTOK][65]
    float* Qs = Vs + NTOK * KVPAD;        // [8][4][64]

    const int b = blockIdx.x, h = blockIdx.y;
    const int tid = threadIdx.x, lane = tid & 31, warp = tid >> 5;

    for (int idx = tid; idx < NTOK * HD; idx += 256) {
        const int j = idx >> 6, d = idx & 63;
        const size_t g = ((size_t)j * BATCH + b) * (3 * CDIM) + h * HD + d;
        Ks[j * KVPAD + d] = qkv[g + CDIM];
        Vs[j * KVPAD + d] = qkv[g + 2 * CDIM];
    }
    __syncthreads();

    for (int g = 0; g < 7; g++) {
        #pragma unroll
        for (int e = 0; e < 4; e++) {
            const int i = warp + 32 * g + 8 * e;
            if (i < NTOK) {
                const size_t qg = ((size_t)i * BATCH + b) * (3 * CDIM) + h * HD;
                Qs[(warp * 4 + e) * HD + lane]      = qkv[qg + lane];
                Qs[(warp * 4 + e) * HD + lane + 32] = qkv[qg + lane + 32];
            }
        }
        __syncwarp();

        float s[4][7];
        #pragma unroll
        for (int e = 0; e < 4; e++)
            #pragma unroll
            for (int t = 0; t < 7; t++) s[e][t] = 0.f;

        #pragma unroll 4
        for (int d = 0; d < HD; d++) {
            const float q0 = Qs[(warp * 4 + 0) * HD + d];
            const float q1 = Qs[(warp * 4 + 1) * HD + d];
            const float q2 = Qs[(warp * 4 + 2) * HD + d];
            const float q3 = Qs[(warp * 4 + 3) * HD + d];
            #pragma unroll
            for (int t = 0; t < 7; t++) {
                const int j = lane + t * 32;
                if (j < NTOK) {
                    const float kv = Ks[j * KVPAD + d];
                    s[0][t] += q0 * kv; s[1][t] += q1 * kv;
                    s[2][t] += q2 * kv; s[3][t] += q3 * kv;
                }
            }
        }

        #pragma unroll
        for (int e = 0; e < 4; e++) {
            float mx = -1e30f;
            #pragma unroll
            for (int t = 0; t < 7; t++) {
                const int j = lane + t * 32;
                s[e][t] = (j < NTOK) ? s[e][t] * 0.125f : -1e30f;
                mx = fmaxf(mx, s[e][t]);
            }
            #pragma unroll
            for (int o = 16; o; o >>= 1)
                mx = fmaxf(mx, __shfl_xor_sync(0xffffffffu, mx, o));
            float sum = 0.f;
            #pragma unroll
            for (int t = 0; t < 7; t++) {
                const int j = lane + t * 32;
                const float ev = (j < NTOK) ? __expf(s[e][t] - mx) : 0.f;
                s[e][t] = ev; sum += ev;
            }
            #pragma unroll
            for (int o = 16; o; o >>= 1)
                sum += __shfl_xor_sync(0xffffffffu, sum, o);
            const float inv = 1.f / sum;
            #pragma unroll
            for (int t = 0; t < 7; t++) s[e][t] *= inv;
        }

        float a0[4] = {}, a1[4] = {};
        #pragma unroll
        for (int t = 0; t < 7; t++) {
            const int jmax = (t == 6) ? (NTOK - 6 * 32) : 32;
            for (int jj = 0; jj < jmax; jj++) {
                const int j = t * 32 + jj;
                const float v0 = Vs[j * KVPAD + lane];
                const float v1 = Vs[j * KVPAD + lane + 32];
                #pragma unroll
                for (int e = 0; e < 4; e++) {
                    const float p = __shfl_sync(0xffffffffu, s[e][t], jj);
                    a0[e] += p * v0; a1[e] += p * v1;
                }
            }
        }

        #pragma unroll
        for (int e = 0; e < 4; e++) {
            const int i = warp + 32 * g + 8 * e;
            if (i < NTOK) {
                const size_t og = ((size_t)i * BATCH + b) * CDIM + h * HD;
                outf[og + lane]      = __float2half_rn(a0[e]);
                outf[og + lane + 32] = __float2half_rn(a1[e]);
            }
        }
        __syncwarp();
    }
}

// ---------------- CLS scores in fp64 straight from ln1 + weights ------------
__global__ void __launch_bounds__(256)
cls_score_kernel(const float* __restrict__ ln1, const float* __restrict__ inw,
                 const float* __restrict__ inb, float* __restrict__ cls)
{
    const int b = blockIdx.x, tid = threadIdx.x;
    const int lane = tid & 31, w = tid >> 5;
    __shared__ float  ln0[CDIM];
    __shared__ double q0[HD];
    __shared__ double wv[CDIM];
    __shared__ double sj[NTOK];
    __shared__ double redd[8];
    __shared__ double beta_s;

    for (int c = tid; c < CDIM; c += 256)
        ln0[c] = ln1[(size_t)b * CDIM + c];
    __syncthreads();

    double acc = 0.0;
    for (int h = 0; h < NH; h++) {
        {
            const int d = tid >> 2, part = tid & 3;
            const float* wr = inw + (size_t)(h * HD + d) * CDIM;
            double s = 0.0;
            const int c0 = part * 192;
            for (int c = c0; c < c0 + 192; c++)
                s += (double)ln0[c] * (double)wr[c];
            s += __shfl_xor_sync(0xffffffffu, s, 1);
            s += __shfl_xor_sync(0xffffffffu, s, 2);
            if (part == 0) q0[d] = s + (double)inb[h * HD + d];
        }
        __syncthreads();
        for (int c = tid; c < CDIM; c += 256) {
            double s = 0.0;
            #pragma unroll 8
            for (int d = 0; d < HD; d++)
                s += q0[d] * (double)inw[(size_t)(CDIM + h * HD + d) * CDIM + c];
            wv[c] = s;
        }
        if (tid == 0) {
            double bsum = 0.0;
            for (int d = 0; d < HD; d++)
                bsum += q0[d] * (double)inb[CDIM + h * HD + d];
            beta_s = bsum;
        }
        __syncthreads();
        for (int j = w; j < NTOK; j += 8) {
            const float* xr = ln1 + ((size_t)j * BATCH + b) * CDIM;
            double s = 0.0;
            for (int c = lane; c < CDIM; c += 32)
                s += (double)xr[c] * wv[c];
            #pragma unroll
            for (int o = 16; o; o >>= 1) s += __shfl_xor_sync(0xffffffffu, s, o);
            if (lane == 0) sj[j] = (s + beta_s) * 0.125;
        }
        __syncthreads();
        double v = (tid < NTOK) ? sj[tid] : -1e300;
        #pragma unroll
        for (int o = 16; o; o >>= 1) v = fmax(v, __shfl_xor_sync(0xffffffffu, v, o));
        if (lane == 0) redd[w] = v;
        __syncthreads();
        double mx = redd[0];
        #pragma unroll
        for (int i = 1; i < 8; i++) mx = fmax(mx, redd[i]);
        const double e = (tid < NTOK) ? exp(sj[tid] - mx) : 0.0;
        double sv = e;
        #pragma unroll
        for (int o = 16; o; o >>= 1) sv += __shfl_xor_sync(0xffffffffu, sv, o);
        __syncthreads();
        if (lane == 0) redd[w] = sv;
        __syncthreads();
        double S = 0.0;
        #pragma unroll
        for (int i = 0; i < 8; i++) S += redd[i];
        if (tid >= 1 && tid < NTOK) acc += e / S;
        __syncthreads();
    }
    if (tid >= 1 && tid < NTOK)
        cls[(size_t)b * NP + (tid - 1)] = (float)(acc * (1.0 / NH));
}

// ---------------- exact stable top-k (value desc, index asc ties) -----------
__global__ void topk_kernel(const float* __restrict__ cls,
                            int* __restrict__ idx, int* __restrict__ comp)
{
    __shared__ float v[NP];
    const int b = blockIdx.x, t = threadIdx.x;
    if (t < NP) v[t] = cls[b * NP + t];
    __syncthreads();
    if (t < NP) {
        const float mv = v[t];
        int r = 0;
        for (int j = 0; j < NP; j++) {
            const float vj = v[j];
            r += (vj > mv) || (vj == mv && j < t);
        }
        if (r < LKEEP) idx[b * LKEEP + r] = t;
        else           comp[b * LKEEP + (r - LKEEP)] = t;
    }
}

// ---------------- build x_new: [cls, topk tokens (desc), fused token] -------
__global__ void gather_kernel(const float* __restrict__ xres,
                              const int* __restrict__ idx,
                              const int* __restrict__ comp,
                              const float* __restrict__ cls,
                              float* __restrict__ xnew)
{
    const int nn = blockIdx.x;
    const int b  = blockIdx.y;
    const int t  = threadIdx.x;
    float* dst = xnew + ((size_t)nn * BATCH + b) * CDIM;

    if (nn == 0) {
        const float* src = xres + (size_t)b * CDIM;
        dst[t] = src[t]; dst[t + 256] = src[t + 256]; dst[t + 512] = src[t + 512];
    } else if (nn <= LKEEP) {
        const int tok = 1 + idx[b * LKEEP + (nn - 1)];
        const float* src = xres + ((size_t)tok * BATCH + b) * CDIM;
        dst[t] = src[t]; dst[t + 256] = src[t + 256]; dst[t + 512] = src[t + 512];
    } else {
        float a0 = 0.f, a1 = 0.f, a2 = 0.f;
        for (int q = 0; q < LKEEP; q++) {
            const int j = comp[b * LKEEP + q];
            const float w = cls[b * NP + j];
            const float* src = xres + ((size_t)(1 + j) * BATCH + b) * CDIM;
            a0 += src[t] * w; a1 += src[t + 256] * w; a2 += src[t + 512] * w;
        }
        dst[t] = a0; dst[t + 256] = a1; dst[t + 512] = a2;
    }
}

// ---------------- launch ----------------------------------------------------
extern "C" void kernel_launch(void* const* d_in, const int* in_sizes, int n_in,
                              void* d_out, int out_size)
{
    const float* x     = (const float*)d_in[0];
    const float* ln1_g = (const float*)d_in[1];
    const float* ln1_b = (const float*)d_in[2];
    const float* in_w  = (const float*)d_in[3];
    const float* in_b  = (const float*)d_in[4];
    const float* ow    = (const float*)d_in[5];
    const float* ob    = (const float*)d_in[6];
    const float* ln2_g = (const float*)d_in[7];
    const float* ln2_b = (const float*)d_in[8];
    const float* fc_w  = (const float*)d_in[9];
    const float* fc_b  = (const float*)d_in[10];
    const float* pj_w  = (const float*)d_in[11];
    const float* pj_b  = (const float*)d_in[12];
    float* out = (float*)d_out;

    float *ln1, *qkv, *xres, *cls, *xnew;
    int *idxp, *compp;
    f16 *ln1f, *attf, *ln2f, *fcf, *wf;
    cudaGetSymbolAddress((void**)&ln1,   g_ln1);
    cudaGetSymbolAddress((void**)&qkv,   g_qkv);
    cudaGetSymbolAddress((void**)&xres,  g_xres);
    cudaGetSymbolAddress((void**)&cls,   g_cls);
    cudaGetSymbolAddress((void**)&idxp,  g_idx);
    cudaGetSymbolAddress((void**)&compp, g_comp);
    cudaGetSymbolAddress((void**)&xnew,  g_xnew);
    cudaGetSymbolAddress((void**)&ln1f,  g_ln1f);
    cudaGetSymbolAddress((void**)&attf,  g_attf);
    cudaGetSymbolAddress((void**)&ln2f,  g_ln2f);
    cudaGetSymbolAddress((void**)&fcf,   g_fcf);
    cudaGetSymbolAddress((void**)&wf,    g_wf);

    cudaFuncSetAttribute(attn_kernel, cudaFuncAttributeMaxDynamicSharedMemorySize,
                         ATT_SMEM);
    cudaFuncSetAttribute(f16_gemm_kernel, cudaFuncAttributeMaxDynamicSharedMemorySize,
                         GSM);

    // 0) weights -> fp16
    convert_w_kernel<<<(3 * CDIM * CDIM / 4 + 255) / 256, 256>>>(
        in_w, wf + O_INW, 3 * CDIM * CDIM / 4);
    convert_w_kernel<<<(CDIM * CDIM / 4 + 255) / 256, 256>>>(
        ow, wf + O_OW, CDIM * CDIM / 4);
    convert_w_kernel<<<(4 * CDIM * CDIM / 4 + 255) / 256, 256>>>(
        fc_w, wf + O_FCW, 4 * CDIM * CDIM / 4);
    convert_w_kernel<<<(4 * CDIM * CDIM / 4 + 255) / 256, 256>>>(
        pj_w, wf + O_PJW, 4 * CDIM * CDIM / 4);

    // 1) ln1 (fp32 for cls path + fp16 for GEMM)
    ln_kernel<<<M1, 256>>>(x, ln1_g, ln1_b, ln1, ln1f);
    // 2) qkv = ln1 @ in_proj_w^T + b
    f16_gemm_kernel<<<dim3(3 * CDIM / 128, M1 / 128), 256, GSM>>>(
        ln1f, wf + O_INW, in_b, nullptr,
        qkv, nullptr, M1, 3 * CDIM, CDIM, 0);
    // 3) attention -> att fp16
    attn_kernel<<<dim3(BATCH, NH), 256, ATT_SMEM>>>(qkv, attf);
    // 4) CLS scores in fp64 (exact, GEMM-independent ranking)
    cls_score_kernel<<<BATCH, 256>>>(ln1, in_w, in_b, cls);
    // 5) out_proj + residual x -> xres
    f16_gemm_kernel<<<dim3(CDIM / 128, M1 / 128), 256, GSM>>>(
        attf, wf + O_OW, ob, x,
        xres, nullptr, M1, CDIM, CDIM, 0);
    // 6) top-k + complement
    topk_kernel<<<BATCH, 256>>>(cls, idxp, compp);
    // 7) build x_new
    gather_kernel<<<dim3(NNEW, BATCH), 256>>>(xres, idxp, compp, cls, xnew);
    // 8) ln2 -> fp16
    ln_kernel<<<M2, 256>>>(xnew, ln2_g, ln2_b, nullptr, ln2f);
    // 9) fc + quickgelu -> fp16
    f16_gemm_kernel<<<dim3(4 * CDIM / 128, M2 / 128), 256, GSM>>>(
        ln2f, wf + O_FCW, fc_b, nullptr,
        nullptr, fcf, M2, 4 * CDIM, CDIM, 1);
    // 10) proj + residual x_new -> out
    f16_gemm_kernel<<<dim3(CDIM / 128, M2 / 128), 256, GSM>>>(
        fcf, wf + O_PJW, pj_b, xnew,
        out, nullptr, M2, CDIM, 4 * CDIM, 0);
}

// round 9
// speedup vs baseline: 2.2861x; 1.1938x over previous
#include <cuda_runtime.h>
#include <cuda_fp16.h>
#include <math.h>
#include <stdint.h>

#define NTOK  197
#define BATCH 256
#define CDIM  768
#define NH    12
#define HD    64
#define LKEEP 98
#define NP    (NTOK - 1)     // 196
#define NNEW  (LKEEP + 2)    // 100
#define M1    (NTOK * BATCH) // 50432
#define M2    (NNEW * BATCH) // 25600

typedef __half f16;

// ---------------- scratch (device globals; no cudaMalloc allowed) ----------
__device__ float g_ln1 [(size_t)M1 * CDIM];          // fp32 (cls path)
__device__ float g_xres[(size_t)M1 * CDIM];
__device__ float g_cls [(size_t)BATCH * NP];
__device__ int   g_idx [BATCH * LKEEP];
__device__ int   g_comp[BATCH * LKEEP];
__device__ float g_xnew[(size_t)M2 * CDIM];

__device__ f16 g_ln1f[(size_t)M1 * CDIM];
__device__ f16 g_qkvf[(size_t)M1 * 3 * CDIM];
__device__ f16 g_attf[(size_t)M1 * CDIM];
__device__ f16 g_ln2f[(size_t)M2 * CDIM];
__device__ f16 g_fcf [(size_t)M2 * 4 * CDIM];
// weights concatenated: in_w | out_w | fc_w | pj_w  (single fp16)
#define O_INW 0
#define O_OW  (3 * CDIM * CDIM)
#define O_FCW (O_OW + CDIM * CDIM)
#define O_PJW (O_FCW + 4 * CDIM * CDIM)
#define W_TOT (O_PJW + 4 * CDIM * CDIM)
__device__ f16 g_wf[W_TOT];

// ---------------- helpers ----------------------------------------------------
__device__ __forceinline__ uint32_t smem_u32(const void* p) {
    uint32_t a;
    asm("{ .reg .u64 t; cvta.to.shared.u64 t, %1; cvt.u32.u64 %0, t; }"
        : "=r"(a) : "l"(p));
    return a;
}
__device__ __forceinline__ void ldsm4(uint32_t r[4], uint32_t addr) {
    asm volatile("ldmatrix.sync.aligned.m8n8.x4.shared.b16 {%0,%1,%2,%3}, [%4];"
        : "=r"(r[0]), "=r"(r[1]), "=r"(r[2]), "=r"(r[3]) : "r"(addr));
}
__device__ __forceinline__ void ldsm4t(uint32_t r[4], uint32_t addr) {
    asm volatile("ldmatrix.sync.aligned.m8n8.x4.trans.shared.b16 {%0,%1,%2,%3}, [%4];"
        : "=r"(r[0]), "=r"(r[1]), "=r"(r[2]), "=r"(r[3]) : "r"(addr));
}
__device__ __forceinline__ void ldsm2(uint32_t r[2], uint32_t addr) {
    asm volatile("ldmatrix.sync.aligned.m8n8.x2.shared.b16 {%0,%1}, [%2];"
        : "=r"(r[0]), "=r"(r[1]) : "r"(addr));
}
__device__ __forceinline__ void mma_f16(float c[4], const uint32_t a[4],
                                        const uint32_t b[2]) {
    asm volatile("mma.sync.aligned.m16n8k16.row.col.f32.f16.f16.f32 "
        "{%0,%1,%2,%3}, {%4,%5,%6,%7}, {%8,%9}, {%0,%1,%2,%3};"
        : "+f"(c[0]), "+f"(c[1]), "+f"(c[2]), "+f"(c[3])
        : "r"(a[0]), "r"(a[1]), "r"(a[2]), "r"(a[3]), "r"(b[0]), "r"(b[1]));
}
__device__ __forceinline__ void cp16(uint32_t dst, const void* src) {
    asm volatile("cp.async.cg.shared.global [%0], [%1], 16;"
                 :: "r"(dst), "l"(src));
}

// ---------------- fp32 -> fp16 converter -------------------------------------
__global__ void convert_w_kernel(const float* __restrict__ s,
                                 f16* __restrict__ d, int n4)
{
    const int i = blockIdx.x * 256 + threadIdx.x;
    if (i >= n4) return;
    float4 v = ((const float4*)s)[i];
    ((__half2*)d)[2 * i]     = __floats2half2_rn(v.x, v.y);
    ((__half2*)d)[2 * i + 1] = __floats2half2_rn(v.z, v.w);
}

// ---------------- layernorm: one block per row of 768 ----------------------
__global__ void ln_kernel(const float* __restrict__ x,
                          const float* __restrict__ gam,
                          const float* __restrict__ bet,
                          float* __restrict__ y,
                          f16* __restrict__ yf)
{
    const int row = blockIdx.x;
    const int t   = threadIdx.x;
    const float* xr = x + (size_t)row * CDIM;

    float v0 = xr[t], v1 = xr[t + 256], v2 = xr[t + 512];
    float s  = v0 + v1 + v2;
    float ss = v0 * v0 + v1 * v1 + v2 * v2;

    __shared__ float red[16];
    #pragma unroll
    for (int o = 16; o; o >>= 1) {
        s  += __shfl_xor_sync(0xffffffffu, s,  o);
        ss += __shfl_xor_sync(0xffffffffu, ss, o);
    }
    const int warp = t >> 5, lane = t & 31;
    if (lane == 0) { red[warp] = s; red[warp + 8] = ss; }
    __syncthreads();
    float S = 0.f, SS = 0.f;
    #pragma unroll
    for (int i = 0; i < 8; i++) { S += red[i]; SS += red[i + 8]; }

    const float mu  = S * (1.f / CDIM);
    const float var = SS * (1.f / CDIM) - mu * mu;
    const float inv = rsqrtf(var + 1e-5f);

    const size_t base = (size_t)row * CDIM;
    #pragma unroll
    for (int e = 0; e < 3; e++) {
        const int c = t + e * 256;
        const float v = (e == 0 ? v0 : (e == 1 ? v1 : v2));
        const float o = (v - mu) * inv * gam[c] + bet[c];
        if (y) y[base + c] = o;
        yf[base + c] = __float2half_rn(o);
    }
}

// ---------------- fp16 mma.sync GEMM, 4-stage cp.async pipeline -------------
#define ROWB   80
#define TBYTES (128 * ROWB)
#define STG    (2 * TBYTES)
#define NSTAGE 4
#define GSM    (NSTAGE * STG)

__global__ void __launch_bounds__(256)
f16_gemm_kernel(const f16* __restrict__ Af, const f16* __restrict__ Wf,
                const float* __restrict__ bias, const float* __restrict__ res,
                float* __restrict__ Cf, f16* __restrict__ Ch,
                int M, int Nn, int K, int act)
{
    extern __shared__ char dsm[];
    const uint32_t sb = smem_u32(dsm);

    const int tid = threadIdx.x, lane = tid & 31, wid = tid >> 5;
    const int wm = wid >> 2, wn = wid & 3;
    const int m0 = blockIdx.y * 128, n0 = blockIdx.x * 128;

    float acc[4][4][4] = {};

    auto issue = [&](int s, int t) {
        const int k0 = t << 5;
        #pragma unroll
        for (int r = 0; r < 4; r++) {
            const int id = tid + (r << 8);
            const int tensor = id >> 9;
            const int w = id & 511;
            const int row = w >> 2, c4 = w & 3;
            const f16* src = (tensor == 0)
                ? Af + (size_t)(m0 + row) * K + k0 + c4 * 8
                : Wf + (size_t)(n0 + row) * K + k0 + c4 * 8;
            const uint32_t dst = sb + (uint32_t)(s * STG + tensor * TBYTES
                                                 + row * ROWB + c4 * 16);
            cp16(dst, src);
        }
        asm volatile("cp.async.commit_group;" ::: "memory");
    };

    const int nch = K >> 5;
    issue(0, 0);
    issue(1, 1);
    issue(2, 2);

    for (int t = 0; t < nch; t++) {
        asm volatile("cp.async.wait_group 2;" ::: "memory");
        __syncthreads();
        if (t + 3 < nch) issue((t + 3) % NSTAGE, t + 3);
        else asm volatile("cp.async.commit_group;" ::: "memory");

        const uint32_t sA = sb + (uint32_t)((t % NSTAGE) * STG);
        #pragma unroll
        for (int ks = 0; ks < 2; ks++) {
            uint32_t ah[4][4];
            #pragma unroll
            for (int mf = 0; mf < 4; mf++) {
                const uint32_t ra = sA +
                    (uint32_t)((wm * 64 + mf * 16 + (lane & 15)) * ROWB
                               + ks * 32 + ((lane >> 4) << 4));
                ldsm4(ah[mf], ra);
            }
            #pragma unroll
            for (int nf = 0; nf < 4; nf++) {
                const uint32_t rb = sA + TBYTES +
                    (uint32_t)((wn * 32 + nf * 8 + (lane & 7)) * ROWB
                               + ks * 32 + (((lane >> 3) & 1) << 4));
                uint32_t bh[2];
                ldsm2(bh, rb);
                #pragma unroll
                for (int mf = 0; mf < 4; mf++)
                    mma_f16(acc[mf][nf], ah[mf], bh);
            }
        }
    }

    #pragma unroll
    for (int mf = 0; mf < 4; mf++) {
        #pragma unroll
        for (int nf = 0; nf < 4; nf++) {
            const int rr = m0 + wm * 64 + mf * 16 + (lane >> 2);
            const int cc = n0 + wn * 32 + nf * 8 + ((lane & 3) << 1);
            const float b0 = bias[cc], b1 = bias[cc + 1];
            float v0 = acc[mf][nf][0] + b0;
            float v1 = acc[mf][nf][1] + b1;
            float v2 = acc[mf][nf][2] + b0;
            float v3 = acc[mf][nf][3] + b1;
            if (act) {
                v0 = v0 / (1.f + __expf(-1.702f * v0));
                v1 = v1 / (1.f + __expf(-1.702f * v1));
                v2 = v2 / (1.f + __expf(-1.702f * v2));
                v3 = v3 / (1.f + __expf(-1.702f * v3));
            }
            const size_t o0 = (size_t)rr * Nn + cc;
            const size_t o1 = (size_t)(rr + 8) * Nn + cc;
            if (Cf) {
                if (res) {
                    float2 r0 = *(const float2*)(res + o0);
                    float2 r1 = *(const float2*)(res + o1);
                    v0 += r0.x; v1 += r0.y; v2 += r1.x; v3 += r1.y;
                }
                float2 s0; s0.x = v0; s0.y = v1;
                float2 s1; s1.x = v2; s1.y = v3;
                *(float2*)(Cf + o0) = s0;
                *(float2*)(Cf + o1) = s1;
            } else {
                *(__half2*)(Ch + o0) = __floats2half2_rn(v0, v1);
                *(__half2*)(Ch + o1) = __floats2half2_rn(v2, v3);
            }
        }
    }
}

// ---------------- tensor-core attention: one CTA per (b,h) ------------------
// Q/K/V fp16 in smem (pad 208, pitch 72), S = Q@K^T via mma (fp32 acc),
// masked fp32 softmax in registers, P -> fp16 smem, O = P@V via ldsm.trans.
#define TP   208                 // padded token count (13 x 16)
#define QP   72                  // Q/K/V smem pitch (halves)
#define PP   216                 // P smem pitch (halves)
#define ATT_SMEM ((3 * TP * QP + 8 * 16 * PP) * 2)   // 145152 bytes

__global__ void __launch_bounds__(256)
attn_kernel(const f16* __restrict__ qkvf, f16* __restrict__ outf)
{
    extern __shared__ f16 smh[];
    f16* Qs = smh;
    f16* Ks = Qs + TP * QP;
    f16* Vs = Ks + TP * QP;
    f16* Ps = Vs + TP * QP;

    const int b = blockIdx.x, h = blockIdx.y;
    const int tid = threadIdx.x, lane = tid & 31, warp = tid >> 5;
    const uint32_t sQ = smem_u32(Qs), sK = smem_u32(Ks), sV = smem_u32(Vs);
    f16* Pw = Ps + warp * 16 * PP;
    const uint32_t sP = smem_u32(Pw);

    // load Q/K/V rows (16B chunks), zero the pad rows
    for (int it = tid; it < TP * 8 * 3; it += 256) {
        const int t = it / (TP * 8);
        const int rem = it % (TP * 8);
        const int j = rem >> 3, c = rem & 7;
        f16* dst = (t == 0 ? Qs : (t == 1 ? Ks : Vs)) + j * QP + c * 8;
        if (j < NTOK) {
            const f16* src = qkvf + ((size_t)j * BATCH + b) * (3 * CDIM)
                             + t * CDIM + h * HD + c * 8;
            *(uint4*)dst = *(const uint4*)src;
        } else {
            uint4 z; z.x = z.y = z.z = z.w = 0u;
            *(uint4*)dst = z;
        }
    }
    __syncthreads();

    for (int mt = warp; mt < 13; mt += 8) {
        const int mbase = mt * 16;

        // Q A-fragments for the 4 k-steps (HD=64)
        uint32_t aq[4][4];
        #pragma unroll
        for (int ks = 0; ks < 4; ks++) {
            const uint32_t ra = sQ + (uint32_t)(((mbase + (lane & 15)) * QP
                                + ks * 16 + ((lane >> 4) << 3)) * 2);
            ldsm4(aq[ks], ra);
        }

        // S = Q @ K^T : 26 n-tiles of 8 keys
        float sacc[26][4];
        #pragma unroll
        for (int nt = 0; nt < 26; nt++)
            #pragma unroll
            for (int q = 0; q < 4; q++) sacc[nt][q] = 0.f;
        #pragma unroll
        for (int nt = 0; nt < 26; nt++) {
            #pragma unroll
            for (int ks = 0; ks < 4; ks++) {
                uint32_t bk[2];
                const uint32_t rb = sK + (uint32_t)(((nt * 8 + (lane & 7)) * QP
                                    + ks * 16 + (((lane >> 3) & 1) << 3)) * 2);
                ldsm2(bk, rb);
                mma_f16(sacc[nt], aq[ks], bk);
            }
        }

        // masked softmax (fp32, in registers; rows r and r+8 per thread)
        float mx0 = -1e30f, mx1 = -1e30f;
        #pragma unroll
        for (int nt = 0; nt < 26; nt++) {
            const int c = nt * 8 + ((lane & 3) << 1);
            sacc[nt][0] = (c     < NTOK) ? sacc[nt][0] * 0.125f : -1e30f;
            sacc[nt][1] = (c + 1 < NTOK) ? sacc[nt][1] * 0.125f : -1e30f;
            sacc[nt][2] = (c     < NTOK) ? sacc[nt][2] * 0.125f : -1e30f;
            sacc[nt][3] = (c + 1 < NTOK) ? sacc[nt][3] * 0.125f : -1e30f;
            mx0 = fmaxf(mx0, fmaxf(sacc[nt][0], sacc[nt][1]));
            mx1 = fmaxf(mx1, fmaxf(sacc[nt][2], sacc[nt][3]));
        }
        mx0 = fmaxf(mx0, __shfl_xor_sync(0xffffffffu, mx0, 1));
        mx0 = fmaxf(mx0, __shfl_xor_sync(0xffffffffu, mx0, 2));
        mx1 = fmaxf(mx1, __shfl_xor_sync(0xffffffffu, mx1, 1));
        mx1 = fmaxf(mx1, __shfl_xor_sync(0xffffffffu, mx1, 2));
        float sm0 = 0.f, sm1 = 0.f;
        #pragma unroll
        for (int nt = 0; nt < 26; nt++) {
            sacc[nt][0] = __expf(sacc[nt][0] - mx0);
            sacc[nt][1] = __expf(sacc[nt][1] - mx0);
            sacc[nt][2] = __expf(sacc[nt][2] - mx1);
            sacc[nt][3] = __expf(sacc[nt][3] - mx1);
            sm0 += sacc[nt][0] + sacc[nt][1];
            sm1 += sacc[nt][2] + sacc[nt][3];
        }
        sm0 += __shfl_xor_sync(0xffffffffu, sm0, 1);
        sm0 += __shfl_xor_sync(0xffffffffu, sm0, 2);
        sm1 += __shfl_xor_sync(0xffffffffu, sm1, 1);
        sm1 += __shfl_xor_sync(0xffffffffu, sm1, 2);
        const float inv0 = 1.f / sm0, inv1 = 1.f / sm1;

        // normalized P -> fp16 smem (per-warp private tile, pitch 216)
        {
            const int r0 = lane >> 2, cbase = (lane & 3) << 1;
            #pragma unroll
            for (int nt = 0; nt < 26; nt++) {
                const int c = nt * 8 + cbase;
                *(__half2*)(Pw + r0 * PP + c) =
                    __floats2half2_rn(sacc[nt][0] * inv0, sacc[nt][1] * inv0);
                *(__half2*)(Pw + (r0 + 8) * PP + c) =
                    __floats2half2_rn(sacc[nt][2] * inv1, sacc[nt][3] * inv1);
            }
        }
        __syncwarp();

        // O = P @ V : 13 k-tiles (tokens) x 8 n-tiles (dims)
        float oacc[8][4];
        #pragma unroll
        for (int nt = 0; nt < 8; nt++)
            #pragma unroll
            for (int q = 0; q < 4; q++) oacc[nt][q] = 0.f;
        for (int kt = 0; kt < 13; kt++) {
            uint32_t ap[4];
            const uint32_t pa = sP + (uint32_t)((((lane & 15)) * PP
                                + kt * 16 + ((lane >> 4) << 3)) * 2);
            ldsm4(ap, pa);
            #pragma unroll
            for (int np = 0; np < 4; np++) {
                uint32_t bv[4];
                const uint32_t va = sV + (uint32_t)(((kt * 16 + (lane & 15)) * QP
                                    + np * 16 + ((lane >> 4) << 3)) * 2);
                ldsm4t(bv, va);
                mma_f16(oacc[np * 2],     ap, bv);
                mma_f16(oacc[np * 2 + 1], ap, bv + 2);
            }
        }

        // store O rows < 197 as fp16
        const int r0 = mbase + (lane >> 2), r1 = r0 + 8;
        #pragma unroll
        for (int nt = 0; nt < 8; nt++) {
            const int c = h * HD + nt * 8 + ((lane & 3) << 1);
            if (r0 < NTOK)
                *(__half2*)(outf + ((size_t)r0 * BATCH + b) * CDIM + c) =
                    __floats2half2_rn(oacc[nt][0], oacc[nt][1]);
            if (r1 < NTOK)
                *(__half2*)(outf + ((size_t)r1 * BATCH + b) * CDIM + c) =
                    __floats2half2_rn(oacc[nt][2], oacc[nt][3]);
        }
        __syncwarp();
    }
}

// ---------------- CLS scores in fp64 straight from ln1 + weights ------------
__global__ void __launch_bounds__(256)
cls_score_kernel(const float* __restrict__ ln1, const float* __restrict__ inw,
                 const float* __restrict__ inb, float* __restrict__ cls)
{
    const int b = blockIdx.x, tid = threadIdx.x;
    const int lane = tid & 31, w = tid >> 5;
    __shared__ float  ln0[CDIM];
    __shared__ double q0[HD];
    __shared__ double wv[CDIM];
    __shared__ double sj[NTOK];
    __shared__ double redd[8];
    __shared__ double beta_s;

    for (int c = tid; c < CDIM; c += 256)
        ln0[c] = ln1[(size_t)b * CDIM + c];
    __syncthreads();

    double acc = 0.0;
    for (int h = 0; h < NH; h++) {
        {
            const int d = tid >> 2, part = tid & 3;
            const float* wr = inw + (size_t)(h * HD + d) * CDIM;
            double s = 0.0;
            const int c0 = part * 192;
            for (int c = c0; c < c0 + 192; c++)
                s += (double)ln0[c] * (double)wr[c];
            s += __shfl_xor_sync(0xffffffffu, s, 1);
            s += __shfl_xor_sync(0xffffffffu, s, 2);
            if (part == 0) q0[d] = s + (double)inb[h * HD + d];
        }
        __syncthreads();
        for (int c = tid; c < CDIM; c += 256) {
            double s = 0.0;
            #pragma unroll 8
            for (int d = 0; d < HD; d++)
                s += q0[d] * (double)inw[(size_t)(CDIM + h * HD + d) * CDIM + c];
            wv[c] = s;
        }
        if (tid == 0) {
            double bsum = 0.0;
            for (int d = 0; d < HD; d++)
                bsum += q0[d] * (double)inb[CDIM + h * HD + d];
            beta_s = bsum;
        }
        __syncthreads();
        for (int j = w; j < NTOK; j += 8) {
            const float* xr = ln1 + ((size_t)j * BATCH + b) * CDIM;
            double s = 0.0;
            for (int c = lane; c < CDIM; c += 32)
                s += (double)xr[c] * wv[c];
            #pragma unroll
            for (int o = 16; o; o >>= 1) s += __shfl_xor_sync(0xffffffffu, s, o);
            if (lane == 0) sj[j] = (s + beta_s) * 0.125;
        }
        __syncthreads();
        double v = (tid < NTOK) ? sj[tid] : -1e300;
        #pragma unroll
        for (int o = 16; o; o >>= 1) v = fmax(v, __shfl_xor_sync(0xffffffffu, v, o));
        if (lane == 0) redd[w] = v;
        __syncthreads();
        double mx = redd[0];
        #pragma unroll
        for (int i = 1; i < 8; i++) mx = fmax(mx, redd[i]);
        const double e = (tid < NTOK) ? exp(sj[tid] - mx) : 0.0;
        double sv = e;
        #pragma unroll
        for (int o = 16; o; o >>= 1) sv += __shfl_xor_sync(0xffffffffu, sv, o);
        __syncthreads();
        if (lane == 0) redd[w] = sv;
        __syncthreads();
        double S = 0.0;
        #pragma unroll
        for (int i = 0; i < 8; i++) S += redd[i];
        if (tid >= 1 && tid < NTOK) acc += e / S;
        __syncthreads();
    }
    if (tid >= 1 && tid < NTOK)
        cls[(size_t)b * NP + (tid - 1)] = (float)(acc * (1.0 / NH));
}

// ---------------- exact stable top-k (value desc, index asc ties) -----------
__global__ void topk_kernel(const float* __restrict__ cls,
                            int* __restrict__ idx, int* __restrict__ comp)
{
    __shared__ float v[NP];
    const int b = blockIdx.x, t = threadIdx.x;
    if (t < NP) v[t] = cls[b * NP + t];
    __syncthreads();
    if (t < NP) {
        const float mv = v[t];
        int r = 0;
        for (int j = 0; j < NP; j++) {
            const float vj = v[j];
            r += (vj > mv) || (vj == mv && j < t);
        }
        if (r < LKEEP) idx[b * LKEEP + r] = t;
        else           comp[b * LKEEP + (r - LKEEP)] = t;
    }
}

// ---------------- build x_new: [cls, topk tokens (desc), fused token] -------
__global__ void gather_kernel(const float* __restrict__ xres,
                              const int* __restrict__ idx,
                              const int* __restrict__ comp,
                              const float* __restrict__ cls,
                              float* __restrict__ xnew)
{
    const int nn = blockIdx.x;
    const int b  = blockIdx.y;
    const int t  = threadIdx.x;
    float* dst = xnew + ((size_t)nn * BATCH + b) * CDIM;

    if (nn == 0) {
        const float* src = xres + (size_t)b * CDIM;
        dst[t] = src[t]; dst[t + 256] = src[t + 256]; dst[t + 512] = src[t + 512];
    } else if (nn <= LKEEP) {
        const int tok = 1 + idx[b * LKEEP + (nn - 1)];
        const float* src = xres + ((size_t)tok * BATCH + b) * CDIM;
        dst[t] = src[t]; dst[t + 256] = src[t + 256]; dst[t + 512] = src[t + 512];
    } else {
        float a0 = 0.f, a1 = 0.f, a2 = 0.f;
        for (int q = 0; q < LKEEP; q++) {
            const int j = comp[b * LKEEP + q];
            const float w = cls[b * NP + j];
            const float* src = xres + ((size_t)(1 + j) * BATCH + b) * CDIM;
            a0 += src[t] * w; a1 += src[t + 256] * w; a2 += src[t + 512] * w;
        }
        dst[t] = a0; dst[t + 256] = a1; dst[t + 512] = a2;
    }
}

// ---------------- launch ----------------------------------------------------
extern "C" void kernel_launch(void* const* d_in, const int* in_sizes, int n_in,
                              void* d_out, int out_size)
{
    const float* x     = (const float*)d_in[0];
    const float* ln1_g = (const float*)d_in[1];
    const float* ln1_b = (const float*)d_in[2];
    const float* in_w  = (const float*)d_in[3];
    const float* in_b  = (const float*)d_in[4];
    const float* ow    = (const float*)d_in[5];
    const float* ob    = (const float*)d_in[6];
    const float* ln2_g = (const float*)d_in[7];
    const float* ln2_b = (const float*)d_in[8];
    const float* fc_w  = (const float*)d_in[9];
    const float* fc_b  = (const float*)d_in[10];
    const float* pj_w  = (const float*)d_in[11];
    const float* pj_b  = (const float*)d_in[12];
    float* out = (float*)d_out;

    float *ln1, *xres, *cls, *xnew;
    int *idxp, *compp;
    f16 *ln1f, *qkvf, *attf, *ln2f, *fcf, *wf;
    cudaGetSymbolAddress((void**)&ln1,   g_ln1);
    cudaGetSymbolAddress((void**)&xres,  g_xres);
    cudaGetSymbolAddress((void**)&cls,   g_cls);
    cudaGetSymbolAddress((void**)&idxp,  g_idx);
    cudaGetSymbolAddress((void**)&compp, g_comp);
    cudaGetSymbolAddress((void**)&xnew,  g_xnew);
    cudaGetSymbolAddress((void**)&ln1f,  g_ln1f);
    cudaGetSymbolAddress((void**)&qkvf,  g_qkvf);
    cudaGetSymbolAddress((void**)&attf,  g_attf);
    cudaGetSymbolAddress((void**)&ln2f,  g_ln2f);
    cudaGetSymbolAddress((void**)&fcf,   g_fcf);
    cudaGetSymbolAddress((void**)&wf,    g_wf);

    cudaFuncSetAttribute(attn_kernel, cudaFuncAttributeMaxDynamicSharedMemorySize,
                         ATT_SMEM);
    cudaFuncSetAttribute(f16_gemm_kernel, cudaFuncAttributeMaxDynamicSharedMemorySize,
                         GSM);

    // 0) weights -> fp16
    convert_w_kernel<<<(3 * CDIM * CDIM / 4 + 255) / 256, 256>>>(
        in_w, wf + O_INW, 3 * CDIM * CDIM / 4);
    convert_w_kernel<<<(CDIM * CDIM / 4 + 255) / 256, 256>>>(
        ow, wf + O_OW, CDIM * CDIM / 4);
    convert_w_kernel<<<(4 * CDIM * CDIM / 4 + 255) / 256, 256>>>(
        fc_w, wf + O_FCW, 4 * CDIM * CDIM / 4);
    convert_w_kernel<<<(4 * CDIM * CDIM / 4 + 255) / 256, 256>>>(
        pj_w, wf + O_PJW, 4 * CDIM * CDIM / 4);

    // 1) ln1 (fp32 for cls path + fp16 for GEMM)
    ln_kernel<<<M1, 256>>>(x, ln1_g, ln1_b, ln1, ln1f);
    // 2) qkv = ln1 @ in_proj_w^T + b -> fp16
    f16_gemm_kernel<<<dim3(3 * CDIM / 128, M1 / 128), 256, GSM>>>(
        ln1f, wf + O_INW, in_b, nullptr,
        nullptr, qkvf, M1, 3 * CDIM, CDIM, 0);
    // 3) tensor-core attention -> att fp16
    attn_kernel<<<dim3(BATCH, NH), 256, ATT_SMEM>>>(qkvf, attf);
    // 4) CLS scores in fp64 (exact, GEMM-independent ranking)
    cls_score_kernel<<<BATCH, 256>>>(ln1, in_w, in_b, cls);
    // 5) out_proj + residual x -> xres
    f16_gemm_kernel<<<dim3(CDIM / 128, M1 / 128), 256, GSM>>>(
        attf, wf + O_OW, ob, x,
        xres, nullptr, M1, CDIM, CDIM, 0);
    // 6) top-k + complement
    topk_kernel<<<BATCH, 256>>>(cls, idxp, compp);
    // 7) build x_new
    gather_kernel<<<dim3(NNEW, BATCH), 256>>>(xres, idxp, compp, cls, xnew);
    // 8) ln2 -> fp16
    ln_kernel<<<M2, 256>>>(xnew, ln2_g, ln2_b, nullptr, ln2f);
    // 9) fc + quickgelu -> fp16
    f16_gemm_kernel<<<dim3(4 * CDIM / 128, M2 / 128), 256, GSM>>>(
        ln2f, wf + O_FCW, fc_b, nullptr,
        nullptr, fcf, M2, 4 * CDIM, CDIM, 1);
    // 10) proj + residual x_new -> out
    f16_gemm_kernel<<<dim3(CDIM / 128, M2 / 128), 256, GSM>>>(
        fcf, wf + O_PJW, pj_b, xnew,
        out, nullptr, M2, CDIM, 4 * CDIM, 0);
}

// round 10
// speedup vs baseline: 2.2942x; 1.0035x over previous
#include <cuda_runtime.h>
#include <cuda_fp16.h>
#include <math.h>
#include <stdint.h>

#define NTOK  197
#define BATCH 256
#define CDIM  768
#define NH    12
#define HD    64
#define LKEEP 98
#define NP    (NTOK - 1)     // 196
#define NNEW  (LKEEP + 2)    // 100
#define M1    (NTOK * BATCH) // 50432
#define M2    (NNEW * BATCH) // 25600

typedef __half f16;

// ---------------- scratch (device globals; no cudaMalloc allowed) ----------
__device__ float g_ln1 [(size_t)M1 * CDIM];          // fp32 (cls path)
__device__ float g_xres[(size_t)M1 * CDIM];
__device__ float g_cls [(size_t)BATCH * NP];
__device__ int   g_idx [BATCH * LKEEP];
__device__ int   g_comp[BATCH * LKEEP];
__device__ float g_xnew[(size_t)M2 * CDIM];

__device__ f16 g_ln1f[(size_t)M1 * CDIM];
__device__ f16 g_qkvf[(size_t)M1 * 3 * CDIM];
__device__ f16 g_attf[(size_t)M1 * CDIM];
__device__ f16 g_ln2f[(size_t)M2 * CDIM];
__device__ f16 g_fcf [(size_t)M2 * 4 * CDIM];
// weights concatenated: in_w | out_w | fc_w | pj_w  (single fp16)
#define O_INW 0
#define O_OW  (3 * CDIM * CDIM)
#define O_FCW (O_OW + CDIM * CDIM)
#define O_PJW (O_FCW + 4 * CDIM * CDIM)
#define W_TOT (O_PJW + 4 * CDIM * CDIM)
__device__ f16 g_wf[W_TOT];

// ---------------- helpers ----------------------------------------------------
__device__ __forceinline__ uint32_t smem_u32(const void* p) {
    uint32_t a;
    asm("{ .reg .u64 t; cvta.to.shared.u64 t, %1; cvt.u32.u64 %0, t; }"
        : "=r"(a) : "l"(p));
    return a;
}
__device__ __forceinline__ void ldsm4(uint32_t r[4], uint32_t addr) {
    asm volatile("ldmatrix.sync.aligned.m8n8.x4.shared.b16 {%0,%1,%2,%3}, [%4];"
        : "=r"(r[0]), "=r"(r[1]), "=r"(r[2]), "=r"(r[3]) : "r"(addr));
}
__device__ __forceinline__ void ldsm4t(uint32_t r[4], uint32_t addr) {
    asm volatile("ldmatrix.sync.aligned.m8n8.x4.trans.shared.b16 {%0,%1,%2,%3}, [%4];"
        : "=r"(r[0]), "=r"(r[1]), "=r"(r[2]), "=r"(r[3]) : "r"(addr));
}
__device__ __forceinline__ void mma_f16(float c[4], const uint32_t a[4],
                                        const uint32_t b[2]) {
    asm volatile("mma.sync.aligned.m16n8k16.row.col.f32.f16.f16.f32 "
        "{%0,%1,%2,%3}, {%4,%5,%6,%7}, {%8,%9}, {%0,%1,%2,%3};"
        : "+f"(c[0]), "+f"(c[1]), "+f"(c[2]), "+f"(c[3])
        : "r"(a[0]), "r"(a[1]), "r"(a[2]), "r"(a[3]), "r"(b[0]), "r"(b[1]));
}
__device__ __forceinline__ void cp16(uint32_t dst, const void* src) {
    asm volatile("cp.async.cg.shared.global [%0], [%1], 16;"
                 :: "r"(dst), "l"(src));
}
__device__ __forceinline__ uint32_t pack_h2(float a, float b) {
    __half2 h = __floats2half2_rn(a, b);
    return *reinterpret_cast<uint32_t*>(&h);
}

// ---------------- fp32 -> fp16 converter -------------------------------------
__global__ void convert_w_kernel(const float* __restrict__ s,
                                 f16* __restrict__ d, int n4)
{
    const int i = blockIdx.x * 256 + threadIdx.x;
    if (i >= n4) return;
    float4 v = ((const float4*)s)[i];
    ((__half2*)d)[2 * i]     = __floats2half2_rn(v.x, v.y);
    ((__half2*)d)[2 * i + 1] = __floats2half2_rn(v.z, v.w);
}

// ---------------- layernorm: one block per row of 768 ----------------------
__global__ void ln_kernel(const float* __restrict__ x,
                          const float* __restrict__ gam,
                          const float* __restrict__ bet,
                          float* __restrict__ y,
                          f16* __restrict__ yf)
{
    const int row = blockIdx.x;
    const int t   = threadIdx.x;
    const float* xr = x + (size_t)row * CDIM;

    float v0 = xr[t], v1 = xr[t + 256], v2 = xr[t + 512];
    float s  = v0 + v1 + v2;
    float ss = v0 * v0 + v1 * v1 + v2 * v2;

    __shared__ float red[16];
    #pragma unroll
    for (int o = 16; o; o >>= 1) {
        s  += __shfl_xor_sync(0xffffffffu, s,  o);
        ss += __shfl_xor_sync(0xffffffffu, ss, o);
    }
    const int warp = t >> 5, lane = t & 31;
    if (lane == 0) { red[warp] = s; red[warp + 8] = ss; }
    __syncthreads();
    float S = 0.f, SS = 0.f;
    #pragma unroll
    for (int i = 0; i < 8; i++) { S += red[i]; SS += red[i + 8]; }

    const float mu  = S * (1.f / CDIM);
    const float var = SS * (1.f / CDIM) - mu * mu;
    const float inv = rsqrtf(var + 1e-5f);

    const size_t base = (size_t)row * CDIM;
    #pragma unroll
    for (int e = 0; e < 3; e++) {
        const int c = t + e * 256;
        const float v = (e == 0 ? v0 : (e == 1 ? v1 : v2));
        const float o = (v - mu) * inv * gam[c] + bet[c];
        if (y) y[base + c] = o;
        yf[base + c] = __float2half_rn(o);
    }
}

// ---------------- fp16 mma.sync GEMM, 4-stage cp.async pipeline -------------
#define ROWB   80
#define TBYTES (128 * ROWB)
#define STG    (2 * TBYTES)
#define NSTAGE 4
#define GSM    (NSTAGE * STG)

__global__ void __launch_bounds__(256)
f16_gemm_kernel(const f16* __restrict__ Af, const f16* __restrict__ Wf,
                const float* __restrict__ bias, const float* __restrict__ res,
                float* __restrict__ Cf, f16* __restrict__ Ch,
                int M, int Nn, int K, int act)
{
    extern __shared__ char dsm[];
    const uint32_t sb = smem_u32(dsm);

    const int tid = threadIdx.x, lane = tid & 31, wid = tid >> 5;
    const int wm = wid >> 2, wn = wid & 3;
    const int m0 = blockIdx.y * 128, n0 = blockIdx.x * 128;

    float acc[4][4][4] = {};

    auto issue = [&](int s, int t) {
        const int k0 = t << 5;
        #pragma unroll
        for (int r = 0; r < 4; r++) {
            const int id = tid + (r << 8);
            const int tensor = id >> 9;
            const int w = id & 511;
            const int row = w >> 2, c4 = w & 3;
            const f16* src = (tensor == 0)
                ? Af + (size_t)(m0 + row) * K + k0 + c4 * 8
                : Wf + (size_t)(n0 + row) * K + k0 + c4 * 8;
            const uint32_t dst = sb + (uint32_t)(s * STG + tensor * TBYTES
                                                 + row * ROWB + c4 * 16);
            cp16(dst, src);
        }
        asm volatile("cp.async.commit_group;" ::: "memory");
    };

    const int nch = K >> 5;
    issue(0, 0);
    issue(1, 1);
    issue(2, 2);

    for (int t = 0; t < nch; t++) {
        asm volatile("cp.async.wait_group 2;" ::: "memory");
        __syncthreads();
        if (t + 3 < nch) issue((t + 3) % NSTAGE, t + 3);
        else asm volatile("cp.async.commit_group;" ::: "memory");

        const uint32_t sA = sb + (uint32_t)((t % NSTAGE) * STG);
        #pragma unroll
        for (int ks = 0; ks < 2; ks++) {
            uint32_t ah[4][4];
            #pragma unroll
            for (int mf = 0; mf < 4; mf++) {
                const uint32_t ra = sA +
                    (uint32_t)((wm * 64 + mf * 16 + (lane & 15)) * ROWB
                               + ks * 32 + ((lane >> 4) << 4));
                ldsm4(ah[mf], ra);
            }
            #pragma unroll
            for (int pair = 0; pair < 2; pair++) {
                // ldsm4 covers two adjacent n-tiles (16 B-rows)
                uint32_t bh4[4];
                const uint32_t rb = sA + TBYTES +
                    (uint32_t)((wn * 32 + pair * 16 + (lane & 7)
                                + ((lane >> 4) << 3)) * ROWB
                               + ks * 32 + (((lane >> 3) & 1) << 4));
                ldsm4(bh4, rb);
                #pragma unroll
                for (int mf = 0; mf < 4; mf++) {
                    mma_f16(acc[mf][pair * 2],     ah[mf], bh4);
                    mma_f16(acc[mf][pair * 2 + 1], ah[mf], bh4 + 2);
                }
            }
        }
    }

    #pragma unroll
    for (int mf = 0; mf < 4; mf++) {
        #pragma unroll
        for (int nf = 0; nf < 4; nf++) {
            const int rr = m0 + wm * 64 + mf * 16 + (lane >> 2);
            const int cc = n0 + wn * 32 + nf * 8 + ((lane & 3) << 1);
            const float b0 = bias[cc], b1 = bias[cc + 1];
            float v0 = acc[mf][nf][0] + b0;
            float v1 = acc[mf][nf][1] + b1;
            float v2 = acc[mf][nf][2] + b0;
            float v3 = acc[mf][nf][3] + b1;
            if (act) {
                v0 = v0 / (1.f + __expf(-1.702f * v0));
                v1 = v1 / (1.f + __expf(-1.702f * v1));
                v2 = v2 / (1.f + __expf(-1.702f * v2));
                v3 = v3 / (1.f + __expf(-1.702f * v3));
            }
            const size_t o0 = (size_t)rr * Nn + cc;
            const size_t o1 = (size_t)(rr + 8) * Nn + cc;
            if (Cf) {
                if (res) {
                    float2 r0 = *(const float2*)(res + o0);
                    float2 r1 = *(const float2*)(res + o1);
                    v0 += r0.x; v1 += r0.y; v2 += r1.x; v3 += r1.y;
                }
                float2 s0; s0.x = v0; s0.y = v1;
                float2 s1; s1.x = v2; s1.y = v3;
                *(float2*)(Cf + o0) = s0;
                *(float2*)(Cf + o1) = s1;
            } else {
                *(__half2*)(Ch + o0) = __floats2half2_rn(v0, v1);
                *(__half2*)(Ch + o1) = __floats2half2_rn(v2, v3);
            }
        }
    }
}

// ---------------- tensor-core attention: one CTA per (b,h) ------------------
// Q/K/V fp16 in smem (pad 208, pitch 72). S = Q@K^T via mma; softmax in
// registers; P repacked DIRECTLY from C-fragments into A-fragments (no smem).
#define TP   208
#define QP   72
#define ATT_SMEM (3 * TP * QP * 2)     // 89856 bytes

__global__ void __launch_bounds__(256)
attn_kernel(const f16* __restrict__ qkvf, f16* __restrict__ outf)
{
    extern __shared__ f16 smh[];
    f16* Qs = smh;
    f16* Ks = Qs + TP * QP;
    f16* Vs = Ks + TP * QP;

    const int b = blockIdx.x, h = blockIdx.y;
    const int tid = threadIdx.x, lane = tid & 31, warp = tid >> 5;
    const uint32_t sQ = smem_u32(Qs), sK = smem_u32(Ks), sV = smem_u32(Vs);

    for (int it = tid; it < TP * 8 * 3; it += 256) {
        const int t = it / (TP * 8);
        const int rem = it % (TP * 8);
        const int j = rem >> 3, c = rem & 7;
        f16* dst = (t == 0 ? Qs : (t == 1 ? Ks : Vs)) + j * QP + c * 8;
        if (j < NTOK) {
            const f16* src = qkvf + ((size_t)j * BATCH + b) * (3 * CDIM)
                             + t * CDIM + h * HD + c * 8;
            *(uint4*)dst = *(const uint4*)src;
        } else {
            uint4 z; z.x = z.y = z.z = z.w = 0u;
            *(uint4*)dst = z;
        }
    }
    __syncthreads();

    for (int mt = warp; mt < 13; mt += 8) {
        const int mbase = mt * 16;

        uint32_t aq[4][4];
        #pragma unroll
        for (int ks = 0; ks < 4; ks++) {
            const uint32_t ra = sQ + (uint32_t)(((mbase + (lane & 15)) * QP
                                + ks * 16 + ((lane >> 4) << 3)) * 2);
            ldsm4(aq[ks], ra);
        }

        // S = Q @ K^T : 13 ldsm4-pairs covering 26 n-tiles
        float sacc[26][4];
        #pragma unroll
        for (int nt = 0; nt < 26; nt++)
            #pragma unroll
            for (int q = 0; q < 4; q++) sacc[nt][q] = 0.f;
        #pragma unroll
        for (int np = 0; np < 13; np++) {
            #pragma unroll
            for (int ks = 0; ks < 4; ks++) {
                uint32_t bk[4];
                const uint32_t rb = sK + (uint32_t)(((np * 16 + (lane & 7)
                                    + ((lane >> 4) << 3)) * QP
                                    + ks * 16 + (((lane >> 3) & 1) << 3)) * 2);
                ldsm4(bk, rb);
                mma_f16(sacc[np * 2],     aq[ks], bk);
                mma_f16(sacc[np * 2 + 1], aq[ks], bk + 2);
            }
        }

        // masked softmax (fp32, registers)
        float mx0 = -1e30f, mx1 = -1e30f;
        #pragma unroll
        for (int nt = 0; nt < 26; nt++) {
            const int c = nt * 8 + ((lane & 3) << 1);
            sacc[nt][0] = (c     < NTOK) ? sacc[nt][0] * 0.125f : -1e30f;
            sacc[nt][1] = (c + 1 < NTOK) ? sacc[nt][1] * 0.125f : -1e30f;
            sacc[nt][2] = (c     < NTOK) ? sacc[nt][2] * 0.125f : -1e30f;
            sacc[nt][3] = (c + 1 < NTOK) ? sacc[nt][3] * 0.125f : -1e30f;
            mx0 = fmaxf(mx0, fmaxf(sacc[nt][0], sacc[nt][1]));
            mx1 = fmaxf(mx1, fmaxf(sacc[nt][2], sacc[nt][3]));
        }
        mx0 = fmaxf(mx0, __shfl_xor_sync(0xffffffffu, mx0, 1));
        mx0 = fmaxf(mx0, __shfl_xor_sync(0xffffffffu, mx0, 2));
        mx1 = fmaxf(mx1, __shfl_xor_sync(0xffffffffu, mx1, 1));
        mx1 = fmaxf(mx1, __shfl_xor_sync(0xffffffffu, mx1, 2));
        float sm0 = 0.f, sm1 = 0.f;
        #pragma unroll
        for (int nt = 0; nt < 26; nt++) {
            sacc[nt][0] = __expf(sacc[nt][0] - mx0);
            sacc[nt][1] = __expf(sacc[nt][1] - mx0);
            sacc[nt][2] = __expf(sacc[nt][2] - mx1);
            sacc[nt][3] = __expf(sacc[nt][3] - mx1);
            sm0 += sacc[nt][0] + sacc[nt][1];
            sm1 += sacc[nt][2] + sacc[nt][3];
        }
        sm0 += __shfl_xor_sync(0xffffffffu, sm0, 1);
        sm0 += __shfl_xor_sync(0xffffffffu, sm0, 2);
        sm1 += __shfl_xor_sync(0xffffffffu, sm1, 1);
        sm1 += __shfl_xor_sync(0xffffffffu, sm1, 2);
        const float inv0 = 1.f / sm0, inv1 = 1.f / sm1;

        // O = P @ V : P A-fragments built directly from the C-fragments.
        float oacc[8][4];
        #pragma unroll
        for (int nt = 0; nt < 8; nt++)
            #pragma unroll
            for (int q = 0; q < 4; q++) oacc[nt][q] = 0.f;
        #pragma unroll
        for (int kt = 0; kt < 13; kt++) {
            uint32_t ap[4];
            ap[0] = pack_h2(sacc[2 * kt][0] * inv0, sacc[2 * kt][1] * inv0);
            ap[1] = pack_h2(sacc[2 * kt][2] * inv1, sacc[2 * kt][3] * inv1);
            ap[2] = pack_h2(sacc[2 * kt + 1][0] * inv0, sacc[2 * kt + 1][1] * inv0);
            ap[3] = pack_h2(sacc[2 * kt + 1][2] * inv1, sacc[2 * kt + 1][3] * inv1);
            #pragma unroll
            for (int np = 0; np < 4; np++) {
                uint32_t bv[4];
                const uint32_t va = sV + (uint32_t)(((kt * 16 + (lane & 15)) * QP
                                    + np * 16 + ((lane >> 4) << 3)) * 2);
                ldsm4t(bv, va);
                mma_f16(oacc[np * 2],     ap, bv);
                mma_f16(oacc[np * 2 + 1], ap, bv + 2);
            }
        }

        const int r0 = mbase + (lane >> 2), r1 = r0 + 8;
        #pragma unroll
        for (int nt = 0; nt < 8; nt++) {
            const int c = h * HD + nt * 8 + ((lane & 3) << 1);
            if (r0 < NTOK)
                *(__half2*)(outf + ((size_t)r0 * BATCH + b) * CDIM + c) =
                    __floats2half2_rn(oacc[nt][0], oacc[nt][1]);
            if (r1 < NTOK)
                *(__half2*)(outf + ((size_t)r1 * BATCH + b) * CDIM + c) =
                    __floats2half2_rn(oacc[nt][2], oacc[nt][3]);
        }
    }
}

// ---------------- CLS scores in fp64 straight from ln1 + weights ------------
__global__ void __launch_bounds__(256)
cls_score_kernel(const float* __restrict__ ln1, const float* __restrict__ inw,
                 const float* __restrict__ inb, float* __restrict__ cls)
{
    const int b = blockIdx.x, tid = threadIdx.x;
    const int lane = tid & 31, w = tid >> 5;
    __shared__ float  ln0[CDIM];
    __shared__ double q0[HD];
    __shared__ double wv[CDIM];
    __shared__ double sj[NTOK];
    __shared__ double redd[8];
    __shared__ double beta_s;

    for (int c = tid; c < CDIM; c += 256)
        ln0[c] = ln1[(size_t)b * CDIM + c];
    __syncthreads();

    double acc = 0.0;
    for (int h = 0; h < NH; h++) {
        {
            const int d = tid >> 2, part = tid & 3;
            const float* wr = inw + (size_t)(h * HD + d) * CDIM;
            double s = 0.0;
            const int c0 = part * 192;
            for (int c = c0; c < c0 + 192; c++)
                s += (double)ln0[c] * (double)wr[c];
            s += __shfl_xor_sync(0xffffffffu, s, 1);
            s += __shfl_xor_sync(0xffffffffu, s, 2);
            if (part == 0) q0[d] = s + (double)inb[h * HD + d];
        }
        __syncthreads();
        for (int c = tid; c < CDIM; c += 256) {
            double s = 0.0;
            #pragma unroll 8
            for (int d = 0; d < HD; d++)
                s += q0[d] * (double)inw[(size_t)(CDIM + h * HD + d) * CDIM + c];
            wv[c] = s;
        }
        if (tid == 0) {
            double bsum = 0.0;
            for (int d = 0; d < HD; d++)
                bsum += q0[d] * (double)inb[CDIM + h * HD + d];
            beta_s = bsum;
        }
        __syncthreads();
        for (int j = w; j < NTOK; j += 8) {
            const float* xr = ln1 + ((size_t)j * BATCH + b) * CDIM;
            double s = 0.0;
            for (int c = lane; c < CDIM; c += 32)
                s += (double)xr[c] * wv[c];
            #pragma unroll
            for (int o = 16; o; o >>= 1) s += __shfl_xor_sync(0xffffffffu, s, o);
            if (lane == 0) sj[j] = (s + beta_s) * 0.125;
        }
        __syncthreads();
        double v = (tid < NTOK) ? sj[tid] : -1e300;
        #pragma unroll
        for (int o = 16; o; o >>= 1) v = fmax(v, __shfl_xor_sync(0xffffffffu, v, o));
        if (lane == 0) redd[w] = v;
        __syncthreads();
        double mx = redd[0];
        #pragma unroll
        for (int i = 1; i < 8; i++) mx = fmax(mx, redd[i]);
        const double e = (tid < NTOK) ? exp(sj[tid] - mx) : 0.0;
        double sv = e;
        #pragma unroll
        for (int o = 16; o; o >>= 1) sv += __shfl_xor_sync(0xffffffffu, sv, o);
        __syncthreads();
        if (lane == 0) redd[w] = sv;
        __syncthreads();
        double S = 0.0;
        #pragma unroll
        for (int i = 0; i < 8; i++) S += redd[i];
        if (tid >= 1 && tid < NTOK) acc += e / S;
        __syncthreads();
    }
    if (tid >= 1 && tid < NTOK)
        cls[(size_t)b * NP + (tid - 1)] = (float)(acc * (1.0 / NH));
}

// ---------------- exact stable top-k (value desc, index asc ties) -----------
__global__ void topk_kernel(const float* __restrict__ cls,
                            int* __restrict__ idx, int* __restrict__ comp)
{
    __shared__ float v[NP];
    const int b = blockIdx.x, t = threadIdx.x;
    if (t < NP) v[t] = cls[b * NP + t];
    __syncthreads();
    if (t < NP) {
        const float mv = v[t];
        int r = 0;
        for (int j = 0; j < NP; j++) {
            const float vj = v[j];
            r += (vj > mv) || (vj == mv && j < t);
        }
        if (r < LKEEP) idx[b * LKEEP + r] = t;
        else           comp[b * LKEEP + (r - LKEEP)] = t;
    }
}

// ---------------- gather + fused ln2: builds x_new AND its layernorm --------
__global__ void gather_ln2_kernel(const float* __restrict__ xres,
                                  const int* __restrict__ idx,
                                  const int* __restrict__ comp,
                                  const float* __restrict__ cls,
                                  const float* __restrict__ gam,
                                  const float* __restrict__ bet,
                                  float* __restrict__ xnew,
                                  f16* __restrict__ ln2f)
{
    const int nn = blockIdx.x;
    const int b  = blockIdx.y;
    const int t  = threadIdx.x;
    const size_t rowo = (size_t)nn * BATCH + b;
    float* dst = xnew + rowo * CDIM;

    float v0, v1, v2;
    if (nn == 0) {
        const float* src = xres + (size_t)b * CDIM;
        v0 = src[t]; v1 = src[t + 256]; v2 = src[t + 512];
    } else if (nn <= LKEEP) {
        const int tok = 1 + idx[b * LKEEP + (nn - 1)];
        const float* src = xres + ((size_t)tok * BATCH + b) * CDIM;
        v0 = src[t]; v1 = src[t + 256]; v2 = src[t + 512];
    } else {
        v0 = v1 = v2 = 0.f;
        for (int q = 0; q < LKEEP; q++) {
            const int j = comp[b * LKEEP + q];
            const float w = cls[b * NP + j];
            const float* src = xres + ((size_t)(1 + j) * BATCH + b) * CDIM;
            v0 += src[t] * w; v1 += src[t + 256] * w; v2 += src[t + 512] * w;
        }
    }
    dst[t] = v0; dst[t + 256] = v1; dst[t + 512] = v2;

    // fused layernorm (identical reduction order to ln_kernel)
    float s  = v0 + v1 + v2;
    float ss = v0 * v0 + v1 * v1 + v2 * v2;
    __shared__ float red[16];
    #pragma unroll
    for (int o = 16; o; o >>= 1) {
        s  += __shfl_xor_sync(0xffffffffu, s,  o);
        ss += __shfl_xor_sync(0xffffffffu, ss, o);
    }
    const int warp = t >> 5, lane = t & 31;
    if (lane == 0) { red[warp] = s; red[warp + 8] = ss; }
    __syncthreads();
    float S = 0.f, SS = 0.f;
    #pragma unroll
    for (int i = 0; i < 8; i++) { S += red[i]; SS += red[i + 8]; }
    const float mu  = S * (1.f / CDIM);
    const float var = SS * (1.f / CDIM) - mu * mu;
    const float inv = rsqrtf(var + 1e-5f);

    f16* lr = ln2f + rowo * CDIM;
    lr[t]       = __float2half_rn((v0 - mu) * inv * gam[t]       + bet[t]);
    lr[t + 256] = __float2half_rn((v1 - mu) * inv * gam[t + 256] + bet[t + 256]);
    lr[t + 512] = __float2half_rn((v2 - mu) * inv * gam[t + 512] + bet[t + 512]);
}

// ---------------- launch ----------------------------------------------------
extern "C" void kernel_launch(void* const* d_in, const int* in_sizes, int n_in,
                              void* d_out, int out_size)
{
    const float* x     = (const float*)d_in[0];
    const float* ln1_g = (const float*)d_in[1];
    const float* ln1_b = (const float*)d_in[2];
    const float* in_w  = (const float*)d_in[3];
    const float* in_b  = (const float*)d_in[4];
    const float* ow    = (const float*)d_in[5];
    const float* ob    = (const float*)d_in[6];
    const float* ln2_g = (const float*)d_in[7];
    const float* ln2_b = (const float*)d_in[8];
    const float* fc_w  = (const float*)d_in[9];
    const float* fc_b  = (const float*)d_in[10];
    const float* pj_w  = (const float*)d_in[11];
    const float* pj_b  = (const float*)d_in[12];
    float* out = (float*)d_out;

    float *ln1, *xres, *cls, *xnew;
    int *idxp, *compp;
    f16 *ln1f, *qkvf, *attf, *ln2f, *fcf, *wf;
    cudaGetSymbolAddress((void**)&ln1,   g_ln1);
    cudaGetSymbolAddress((void**)&xres,  g_xres);
    cudaGetSymbolAddress((void**)&cls,   g_cls);
    cudaGetSymbolAddress((void**)&idxp,  g_idx);
    cudaGetSymbolAddress((void**)&compp, g_comp);
    cudaGetSymbolAddress((void**)&xnew,  g_xnew);
    cudaGetSymbolAddress((void**)&ln1f,  g_ln1f);
    cudaGetSymbolAddress((void**)&qkvf,  g_qkvf);
    cudaGetSymbolAddress((void**)&attf,  g_attf);
    cudaGetSymbolAddress((void**)&ln2f,  g_ln2f);
    cudaGetSymbolAddress((void**)&fcf,   g_fcf);
    cudaGetSymbolAddress((void**)&wf,    g_wf);

    cudaFuncSetAttribute(attn_kernel, cudaFuncAttributeMaxDynamicSharedMemorySize,
                         ATT_SMEM);
    cudaFuncSetAttribute(f16_gemm_kernel, cudaFuncAttributeMaxDynamicSharedMemorySize,
                         GSM);

    // 0) weights -> fp16
    convert_w_kernel<<<(3 * CDIM * CDIM / 4 + 255) / 256, 256>>>(
        in_w, wf + O_INW, 3 * CDIM * CDIM / 4);
    convert_w_kernel<<<(CDIM * CDIM / 4 + 255) / 256, 256>>>(
        ow, wf + O_OW, CDIM * CDIM / 4);
    convert_w_kernel<<<(4 * CDIM * CDIM / 4 + 255) / 256, 256>>>(
        fc_w, wf + O_FCW, 4 * CDIM * CDIM / 4);
    convert_w_kernel<<<(4 * CDIM * CDIM / 4 + 255) / 256, 256>>>(
        pj_w, wf + O_PJW, 4 * CDIM * CDIM / 4);

    // 1) ln1 (fp32 for cls path + fp16 for GEMM)
    ln_kernel<<<M1, 256>>>(x, ln1_g, ln1_b, ln1, ln1f);
    // 2) qkv = ln1 @ in_proj_w^T + b -> fp16
    f16_gemm_kernel<<<dim3(3 * CDIM / 128, M1 / 128), 256, GSM>>>(
        ln1f, wf + O_INW, in_b, nullptr,
        nullptr, qkvf, M1, 3 * CDIM, CDIM, 0);
    // 3) tensor-core attention -> att fp16
    attn_kernel<<<dim3(BATCH, NH), 256, ATT_SMEM>>>(qkvf, attf);
    // 4) CLS scores in fp64 (exact, GEMM-independent ranking)
    cls_score_kernel<<<BATCH, 256>>>(ln1, in_w, in_b, cls);
    // 5) out_proj + residual x -> xres
    f16_gemm_kernel<<<dim3(CDIM / 128, M1 / 128), 256, GSM>>>(
        attf, wf + O_OW, ob, x,
        xres, nullptr, M1, CDIM, CDIM, 0);
    // 6) top-k + complement
    topk_kernel<<<BATCH, 256>>>(cls, idxp, compp);
    // 7) build x_new + fused ln2
    gather_ln2_kernel<<<dim3(NNEW, BATCH), 256>>>(
        xres, idxp, compp, cls, ln2_g, ln2_b, xnew, ln2f);
    // 8) fc + quickgelu -> fp16
    f16_gemm_kernel<<<dim3(4 * CDIM / 128, M2 / 128), 256, GSM>>>(
        ln2f, wf + O_FCW, fc_b, nullptr,
        nullptr, fcf, M2, 4 * CDIM, CDIM, 1);
    // 9) proj + residual x_new -> out
    f16_gemm_kernel<<<dim3(CDIM / 128, M2 / 128), 256, GSM>>>(
        fcf, wf + O_PJW, pj_b, xnew,
        out, nullptr, M2, CDIM, 4 * CDIM, 0);
}